// round 9
// baseline (speedup 1.0000x reference)
#include <cuda_runtime.h>
#include <cstdint>

#define N_NODES 25000
#define N_EDGES 320000
#define F       64
#define NHEADS  5
#define NRELS   20
#define NBASES  10
#define OUTC    320
#define PCOLS   200          // GEMM P-columns (compact): 100 s + 100 d
#define PSTRIDE 320          // padded per-node P row: 20 rels * 16
#define TOTC    584          // 64 z + 320 self_z + 200 P
#define CHUNK   32

// ---------------- static device scratch ------------------------------------
__device__ float    g_z [N_NODES * F];          // 6.4 MB
__device__ float    g_W2[64 * PCOLS];
__device__ float    g_P [N_NODES * PSTRIDE];    // 32 MB padded
__device__ int      g_cnt [N_NODES];            // zero at load; self-restored by scan3
__device__ int      g_scan[N_NODES];
__device__ int      g_bsum[32];
__device__ int      g_cur [N_NODES];
__device__ unsigned g_srcrt[N_EDGES];           // src | rel<<16, sorted by dst
__device__ int      g_dstS [N_EDGES];           // dst, sorted

// ---------------- tf32 helpers ----------------------------------------------
__device__ __forceinline__ uint32_t f2tf32(float x) {
    uint32_t u;
    asm("cvt.rn.tf32.f32 %0, %1;" : "=r"(u) : "f"(x));
    return u;
}
__device__ __forceinline__ void tf32_split(float x, uint32_t& hi, uint32_t& lo) {
    hi = f2tf32(x);
    float r = x - __uint_as_float(hi);
    lo = f2tf32(r);
}
__device__ __forceinline__ void mma_tf32(float* d, uint4 a, uint2 b) {
    asm volatile("mma.sync.aligned.m16n8k8.row.col.f32.tf32.tf32.f32 "
                 "{%0,%1,%2,%3}, {%4,%5,%6,%7}, {%8,%9}, {%0,%1,%2,%3};"
                 : "+f"(d[0]), "+f"(d[1]), "+f"(d[2]), "+f"(d[3])
                 : "r"(a.x), "r"(a.y), "r"(a.z), "r"(a.w), "r"(b.x), "r"(b.y));
}

// ---------------------------------------------------------------------------
// K1: attention-weight composition.  One block per relation.
// ---------------------------------------------------------------------------
__global__ void __launch_bounds__(320) attn_comp_kernel(const float* __restrict__ aw,
                                                        const float* __restrict__ w_comp,
                                                        const float* __restrict__ fc_w)
{
    __shared__ float afc[128 * NHEADS];
    const int r = blockIdx.x, tid = threadIdx.x;

    if (tid < 128) {
        float acc[NHEADS] = {};
#pragma unroll
        for (int b = 0; b < NBASES; b++) {
            float wc = w_comp[r * NBASES + b];
#pragma unroll
            for (int h = 0; h < NHEADS; h++)
                acc[h] += wc * aw[(b * 128 + tid) * NHEADS + h];
        }
#pragma unroll
        for (int h = 0; h < NHEADS; h++) afc[tid * NHEADS + h] = acc[h];
    }
    __syncthreads();

    for (int o = tid; o < 640; o += 320) {
        int k = o / 10, c2 = o % 10, h = c2 % 5;
        const float* af = afc + (c2 >= 5 ? 64 * NHEADS : 0) + h;
        float sum = 0.f;
#pragma unroll
        for (int f = 0; f < 64; f++) sum += fc_w[k * 64 + f] * af[f * NHEADS];
        g_W2[k * PCOLS + (c2 >= 5 ? 100 : 0) + r * 5 + h] = sum;
    }
}

// ---------------------------------------------------------------------------
// Sort chain: hist -> scan1 -> scan3(+cnt reset) -> scatter
// ---------------------------------------------------------------------------
__global__ void hist_kernel(const int* __restrict__ dst)
{
    int e = blockIdx.x * blockDim.x + threadIdx.x;
    if (e < N_EDGES) atomicAdd(&g_cnt[dst[e]], 1);
}

__global__ void __launch_bounds__(1024) scan1_kernel()
{
    __shared__ int wsum[32];
    const int tid = threadIdx.x, lane = tid & 31, wid = tid >> 5;
    const int idx = blockIdx.x * 1024 + tid;
    int v = (idx < N_NODES) ? g_cnt[idx] : 0;
    int x = v;
#pragma unroll
    for (int d = 1; d < 32; d <<= 1) {
        int y = __shfl_up_sync(0xffffffffu, x, d);
        if (lane >= d) x += y;
    }
    if (lane == 31) wsum[wid] = x;
    __syncthreads();
    if (tid < 32) {
        int w = wsum[tid];
#pragma unroll
        for (int d = 1; d < 32; d <<= 1) {
            int y = __shfl_up_sync(0xffffffffu, w, d);
            if (tid >= d) w += y;
        }
        wsum[tid] = w;
    }
    __syncthreads();
    int incl = x + (wid > 0 ? wsum[wid - 1] : 0);
    if (idx < N_NODES) g_scan[idx] = incl;
    if (tid == 1023)   g_bsum[blockIdx.x] = incl;
}

__global__ void __launch_bounds__(1024) scan3_kernel()
{
    __shared__ int s_pre;
    const int tid = threadIdx.x;
    if (tid < 32) {
        int v = (tid < blockIdx.x) ? g_bsum[tid] : 0;
#pragma unroll
        for (int d = 16; d > 0; d >>= 1) v += __shfl_xor_sync(0xffffffffu, v, d);
        if (tid == 0) s_pre = v;
    }
    __syncthreads();
    int idx = blockIdx.x * 1024 + tid;
    if (idx < N_NODES) {
        int c = g_cnt[idx];
        g_cur[idx] = g_scan[idx] + s_pre - c;
        g_cnt[idx] = 0;                        // self-restore for next replay
    }
}

__global__ void scatter_kernel(const int* __restrict__ dst,
                               const int* __restrict__ src,
                               const int* __restrict__ et)
{
    int e = blockIdx.x * blockDim.x + threadIdx.x;
    if (e < N_EDGES) {
        int d = dst[e];
        int pos = atomicAdd(&g_cur[d], 1);
        g_srcrt[pos] = (unsigned)src[e] | ((unsigned)et[e] << 16);
        g_dstS[pos]  = d;
    }
}

// ---------------------------------------------------------------------------
// proj_mma v2: tensor-core tf32 3x-split GEMM with FRAGMENT-LAYOUT smem.
// Tile 256 rows x 64 cols, 512 thr (16 warps, warp = m16 x n64).
// Fragments pre-arranged so main loop uses LDS.128 (A) / LDS.64 (B).
// smem: AfragHi/Lo [16 mb][8 ks][32 lane][4]  = 64 KB each
//       BfragHi/Lo [8 j ][8 ks][32 lane][2]  = 16 KB each   -> 160 KB total
// ---------------------------------------------------------------------------
#define AFRAG_WORDS (16 * 8 * 32 * 4)
#define BFRAG_WORDS (8 * 8 * 32 * 2)
#define PROJ_SMEM   ((AFRAG_WORDS * 2 + BFRAG_WORDS * 2) * 4)

__global__ void __launch_bounds__(512) proj_mma_kernel(const float* __restrict__ feat,
                                                       const float* __restrict__ fc_w,
                                                       const float* __restrict__ self_fc_w,
                                                       float* __restrict__ out)
{
    extern __shared__ uint32_t smem[];
    uint32_t* AfH = smem;
    uint32_t* AfL = AfH + AFRAG_WORDS;
    uint32_t* BfH = AfL + AFRAG_WORDS;
    uint32_t* BfL = BfH + BFRAG_WORDS;

    const int tid = threadIdx.x;
    const int m0  = blockIdx.x * 256;
    const int c0  = blockIdx.y * 64;

    // ---- load + split A tile (256 rows x 64 k) into fragment layout
#pragma unroll
    for (int i = 0; i < 8; i++) {
        int v = tid + i * 512;                 // 0..4095 float4 slots
        int row = v >> 4, k4 = (v & 15) * 4;
        int node = m0 + row;
        float4 a = make_float4(0.f, 0.f, 0.f, 0.f);
        if (node < N_NODES) a = *(const float4*)(feat + node * F + k4);
        int mb = row >> 4, rin = row & 15, g = rin & 7, hr = rin >> 3;
        int ks = k4 >> 3,  hk = (k4 & 7) >> 2;
        int qq = hk * 2 + hr;
        uint32_t base = (uint32_t)(((mb * 8 + ks) * 32 + g * 4) * 4 + qq);
        float av[4] = {a.x, a.y, a.z, a.w};
#pragma unroll
        for (int e = 0; e < 4; e++) {
            uint32_t hi, lo;
            tf32_split(av[e], hi, lo);
            AfH[base + e * 4] = hi;
            AfL[base + e * 4] = lo;
        }
    }
    // ---- load + split B tile (64 k x 64 n) into fragment layout
#pragma unroll
    for (int i = 0; i < 2; i++) {
        int v = tid + i * 512;                 // 0..1023 float4 slots
        int k = v >> 4, n4 = (v & 15) * 4;
        int gc = c0 + n4;
        float4 b = make_float4(0.f, 0.f, 0.f, 0.f);
        if (gc < 64)        b = *(const float4*)(fc_w + k * 64 + gc);
        else if (gc < 384)  b = *(const float4*)(self_fc_w + k * 320 + (gc - 64));
        else if (gc < TOTC) b = *(const float4*)(g_W2 + k * PCOLS + (gc - 384));
        int ks = k >> 3, kin = k & 7, tig = kin & 3, q = kin >> 2;
        float bv[4] = {b.x, b.y, b.z, b.w};
#pragma unroll
        for (int e = 0; e < 4; e++) {
            int n = n4 + e;
            int j = n >> 3, g = n & 7;
            uint32_t idx = (uint32_t)((((j * 8 + ks) * 32 + g * 4 + tig) * 2) + q);
            uint32_t hi, lo;
            tf32_split(bv[e], hi, lo);
            BfH[idx] = hi;
            BfL[idx] = lo;
        }
    }
    __syncthreads();

    const int wid  = tid >> 5;
    const int lane = tid & 31;
    const int gid  = lane >> 2;
    const int tig  = lane & 3;

    float d[8][4];
#pragma unroll
    for (int j = 0; j < 8; j++)
#pragma unroll
        for (int q = 0; q < 4; q++) d[j][q] = 0.f;

    const uint32_t* aH = AfH + (wid * 8 * 32 + lane) * 4;
    const uint32_t* aL = AfL + (wid * 8 * 32 + lane) * 4;
    const uint32_t* bH = BfH + lane * 2;
    const uint32_t* bL = BfL + lane * 2;

#pragma unroll
    for (int ks = 0; ks < 8; ks++) {
        uint4 ah = *(const uint4*)(aH + ks * 128);
        uint4 al = *(const uint4*)(aL + ks * 128);
#pragma unroll
        for (int j = 0; j < 8; j++) {
            uint2 bh = *(const uint2*)(bH + (j * 8 + ks) * 64);
            uint2 bl = *(const uint2*)(bL + (j * 8 + ks) * 64);
            mma_tf32(d[j], ah, bh);
            mma_tf32(d[j], al, bh);
            mma_tf32(d[j], ah, bl);
        }
    }

    // ---- epilogue: route to g_z / out / g_P
    const int r0 = m0 + 16 * wid + gid;
    const int cb = tig * 2;
#pragma unroll
    for (int j = 0; j < 8; j++) {
        int gc = c0 + 8 * j + cb;
        if (gc >= TOTC) continue;
#pragma unroll
        for (int half = 0; half < 2; half++) {
            int node = r0 + 8 * half;
            if (node >= N_NODES) continue;
            float x = d[j][2 * half], y = d[j][2 * half + 1];
            if (gc < 64) {
                *(float2*)(g_z + node * F + gc) = make_float2(x, y);
            } else if (gc < 384) {
                *(float2*)(out + node * OUTC + (gc - 64)) = make_float2(x, y);
            } else {
#pragma unroll
                for (int t = 0; t < 2; t++) {
                    int ix = gc - 384 + t;
                    int part = (ix >= 100) ? 8 : 0;
                    int pix  = (ix >= 100) ? ix - 100 : ix;
                    int rr = pix / 5, hh = pix % 5;
                    g_P[node * PSTRIDE + rr * 16 + part + hh] = t ? y : x;
                }
            }
        }
    }
}

// ---------------------------------------------------------------------------
// gather: edge-parallel aggregation over dst-sorted edges (r8, padded P).
// ---------------------------------------------------------------------------
__global__ void __launch_bounds__(256) gather_kernel(float* __restrict__ out)
{
    __shared__ float stage[8][328];
    const int w = threadIdx.x >> 5, lane = threadIdx.x & 31;
    const int gw = blockIdx.x * 8 + w;
    const int e0 = gw * CHUNK;
    if (e0 >= N_EDGES) return;
    const int e1 = min(e0 + CHUNK, N_EDGES);

    float acc[10];
#pragma unroll
    for (int q = 0; q < 10; q++) acc[q] = 0.f;

    int      d_n = g_dstS[e0];
    unsigned pk  = g_srcrt[e0];
    int s_n = pk & 0xFFFFu, r_n = pk >> 16;
    float2 zs_n = *(const float2*)(g_z + s_n * F + 2 * lane);
    const float* pp = g_P + s_n * PSTRIDE + r_n * 16;
    const float* qq = g_P + d_n * PSTRIDE + r_n * 16 + 8;
    float4 ps4_n = *(const float4*)pp;  float ps1_n = pp[4];
    float4 pd4_n = *(const float4*)qq;  float pd1_n = qq[4];
    int d_cur = d_n;

    for (int i = e0; i < e1; i++) {
        const int    d_c  = d_n;
        const float2 zs   = zs_n;
        const float4 ps4  = ps4_n, pd4 = pd4_n;
        const float  ps1  = ps1_n, pd1 = pd1_n;

        if (i + 1 < e1) {
            d_n = g_dstS[i + 1];
            pk  = g_srcrt[i + 1];
            int s2 = pk & 0xFFFFu, r2 = pk >> 16;
            zs_n = *(const float2*)(g_z + s2 * F + 2 * lane);
            const float* p2 = g_P + s2 * PSTRIDE + r2 * 16;
            const float* p3 = g_P + d_n * PSTRIDE + r2 * 16 + 8;
            ps4_n = *(const float4*)p2;  ps1_n = p2[4];
            pd4_n = *(const float4*)p3;  pd1_n = p3[4];
        }

        if (d_c != d_cur) {   // warp-uniform branch
#pragma unroll
            for (int h = 0; h < NHEADS; h++)
                *(float2*)&stage[w][h * F + 2 * lane] = make_float2(acc[2 * h], acc[2 * h + 1]);
            __syncwarp();
            float* ob = out + (long)d_cur * OUTC;
#pragma unroll
            for (int t = 0; t < 3; t++) {
                int cc = lane + 32 * t;
                if (cc < 80) {
                    float4 v = *(const float4*)&stage[w][cc * 4];
                    asm volatile("red.global.add.v4.f32 [%0], {%1, %2, %3, %4};"
                                 :: "l"(ob + 4 * cc), "f"(v.x), "f"(v.y), "f"(v.z), "f"(v.w)
                                 : "memory");
                }
            }
            __syncwarp();
#pragma unroll
            for (int q = 0; q < 10; q++) acc[q] = 0.f;
            d_cur = d_c;
        }

        float a0 = ps4.x + pd4.x;  a0 = a0 > 0.f ? a0 : 0.01f * a0;
        float a1 = ps4.y + pd4.y;  a1 = a1 > 0.f ? a1 : 0.01f * a1;
        float a2 = ps4.z + pd4.z;  a2 = a2 > 0.f ? a2 : 0.01f * a2;
        float a3 = ps4.w + pd4.w;  a3 = a3 > 0.f ? a3 : 0.01f * a3;
        float a4 = ps1   + pd1;    a4 = a4 > 0.f ? a4 : 0.01f * a4;
        acc[0] += a0 * zs.x;  acc[1] += a0 * zs.y;
        acc[2] += a1 * zs.x;  acc[3] += a1 * zs.y;
        acc[4] += a2 * zs.x;  acc[5] += a2 * zs.y;
        acc[6] += a3 * zs.x;  acc[7] += a3 * zs.y;
        acc[8] += a4 * zs.x;  acc[9] += a4 * zs.y;
    }

    // final flush
#pragma unroll
    for (int h = 0; h < NHEADS; h++)
        *(float2*)&stage[w][h * F + 2 * lane] = make_float2(acc[2 * h], acc[2 * h + 1]);
    __syncwarp();
    float* ob = out + (long)d_cur * OUTC;
#pragma unroll
    for (int t = 0; t < 3; t++) {
        int cc = lane + 32 * t;
        if (cc < 80) {
            float4 v = *(const float4*)&stage[w][cc * 4];
            asm volatile("red.global.add.v4.f32 [%0], {%1, %2, %3, %4};"
                         :: "l"(ob + 4 * cc), "f"(v.x), "f"(v.y), "f"(v.z), "f"(v.w)
                         : "memory");
        }
    }
}

// ---------------------------------------------------------------------------
extern "C" void kernel_launch(void* const* d_in, const int* in_sizes, int n_in,
                              void* d_out, int out_size)
{
    const float* feat      = (const float*)d_in[0];
    const int*   src       = (const int*)  d_in[1];
    const int*   dst       = (const int*)  d_in[2];
    const int*   etype     = (const int*)  d_in[3];
    const float* fc_w      = (const float*)d_in[4];
    const float* self_fc_w = (const float*)d_in[5];
    const float* aw        = (const float*)d_in[6];
    const float* w_comp    = (const float*)d_in[7];
    float* out = (float*)d_out;

    const int NB = (N_NODES + 1023) / 1024;   // 25

    cudaFuncSetAttribute(proj_mma_kernel,
                         cudaFuncAttributeMaxDynamicSharedMemorySize, PROJ_SMEM);

    attn_comp_kernel<<<NRELS, 320>>>(aw, w_comp, fc_w);                 // 1
    hist_kernel<<<(N_EDGES + 255) / 256, 256>>>(dst);                   // 2
    scan1_kernel<<<NB, 1024>>>();                                       // 3
    proj_mma_kernel<<<dim3((N_NODES + 255) / 256, 10), 512, PROJ_SMEM>>>(feat, fc_w, self_fc_w, out); // 4 (profiled)
    scan3_kernel<<<NB, 1024>>>();                                       // 5
    scatter_kernel<<<(N_EDGES + 255) / 256, 256>>>(dst, src, etype);    // 6
    gather_kernel<<<(N_EDGES / CHUNK + 7) / 8, 256>>>(out);             // 7
}

// round 10
// speedup vs baseline: 1.1813x; 1.1813x over previous
#include <cuda_runtime.h>
#include <cstdint>

#define N_NODES 25000
#define N_EDGES 320000
#define F       64
#define NHEADS  5
#define NRELS   20
#define NBASES  10
#define OUTC    320
#define PCOLS   200          // GEMM P-columns (compact): 100 s + 100 d
#define PSTRIDE 320          // padded per-node P row: 20 rels * 16
#define TOTC    584          // 64 z + 320 self_z + 200 P
#define WCOLS   640          // padded fused-W width
#define CHUNK   32

// ---------------- static device scratch ------------------------------------
__device__ float    g_z [N_NODES * F];          // 6.4 MB
__device__ float    g_W2[64 * PCOLS];
__device__ float    g_P [N_NODES * PSTRIDE];    // 32 MB padded
__device__ float    g_featH[N_NODES * F];       // 6.4 MB tf32-hi plane of feat
__device__ float    g_featL[N_NODES * F];       // 6.4 MB tf32-lo plane
__device__ float    g_WH[64 * WCOLS];           // fused W hi plane
__device__ float    g_WL[64 * WCOLS];           // fused W lo plane
__device__ int      g_cnt [N_NODES];            // zero at load; self-restored by scan3
__device__ int      g_scan[N_NODES];
__device__ int      g_bsum[32];
__device__ int      g_cur [N_NODES];
__device__ unsigned g_srcrt[N_EDGES];           // src | rel<<16, sorted by dst
__device__ int      g_dstS [N_EDGES];           // dst, sorted

// ---------------- tf32 helpers ----------------------------------------------
__device__ __forceinline__ uint32_t f2tf32(float x) {
    uint32_t u;
    asm("cvt.rn.tf32.f32 %0, %1;" : "=r"(u) : "f"(x));
    return u;
}
__device__ __forceinline__ void tf32_split(float x, uint32_t& hi, uint32_t& lo) {
    hi = f2tf32(x);
    float r = x - __uint_as_float(hi);
    lo = f2tf32(r);
}
__device__ __forceinline__ void mma_tf32(float* d, const uint32_t* a, const uint32_t* b) {
    asm volatile("mma.sync.aligned.m16n8k8.row.col.f32.tf32.tf32.f32 "
                 "{%0,%1,%2,%3}, {%4,%5,%6,%7}, {%8,%9}, {%0,%1,%2,%3};"
                 : "+f"(d[0]), "+f"(d[1]), "+f"(d[2]), "+f"(d[3])
                 : "r"(a[0]), "r"(a[1]), "r"(a[2]), "r"(a[3]), "r"(b[0]), "r"(b[1]));
}

// ---------------------------------------------------------------------------
// K1: attention-weight composition.  One block per relation.
// ---------------------------------------------------------------------------
__global__ void __launch_bounds__(320) attn_comp_kernel(const float* __restrict__ aw,
                                                        const float* __restrict__ w_comp,
                                                        const float* __restrict__ fc_w)
{
    __shared__ float afc[128 * NHEADS];
    const int r = blockIdx.x, tid = threadIdx.x;

    if (tid < 128) {
        float acc[NHEADS] = {};
#pragma unroll
        for (int b = 0; b < NBASES; b++) {
            float wc = w_comp[r * NBASES + b];
#pragma unroll
            for (int h = 0; h < NHEADS; h++)
                acc[h] += wc * aw[(b * 128 + tid) * NHEADS + h];
        }
#pragma unroll
        for (int h = 0; h < NHEADS; h++) afc[tid * NHEADS + h] = acc[h];
    }
    __syncthreads();

    for (int o = tid; o < 640; o += 320) {
        int k = o / 10, c2 = o % 10, h = c2 % 5;
        const float* af = afc + (c2 >= 5 ? 64 * NHEADS : 0) + h;
        float sum = 0.f;
#pragma unroll
        for (int f = 0; f < 64; f++) sum += fc_w[k * 64 + f] * af[f * NHEADS];
        g_W2[k * PCOLS + (c2 >= 5 ? 100 : 0) + r * 5 + h] = sum;
    }
}

// ---------------------------------------------------------------------------
// K2: split fused weight matrix [fc_w | self_fc_w | W2 | 0pad] into tf32 planes.
// grid 64 (k), block 640 (col).
// ---------------------------------------------------------------------------
__global__ void __launch_bounds__(640) split_w_kernel(const float* __restrict__ fc_w,
                                                      const float* __restrict__ self_fc_w)
{
    const int k = blockIdx.x, c = threadIdx.x;
    float x = 0.f;
    if (c < 64)        x = fc_w[k * 64 + c];
    else if (c < 384)  x = self_fc_w[k * 320 + (c - 64)];
    else if (c < TOTC) x = g_W2[k * PCOLS + (c - 384)];
    uint32_t hi, lo;
    tf32_split(x, hi, lo);
    g_WH[k * WCOLS + c] = __uint_as_float(hi);
    g_WL[k * WCOLS + c] = __uint_as_float(lo);
}

// ---------------------------------------------------------------------------
// K3: split feat into tf32 planes (float4 granularity).
// ---------------------------------------------------------------------------
__global__ void __launch_bounds__(256) split_feat_kernel(const float* __restrict__ feat)
{
    int t = blockIdx.x * 256 + threadIdx.x;
    if (t >= N_NODES * F / 4) return;
    float4 v = ((const float4*)feat)[t];
    uint32_t h0, l0, h1, l1, h2, l2, h3, l3;
    tf32_split(v.x, h0, l0);
    tf32_split(v.y, h1, l1);
    tf32_split(v.z, h2, l2);
    tf32_split(v.w, h3, l3);
    ((float4*)g_featH)[t] = make_float4(__uint_as_float(h0), __uint_as_float(h1),
                                        __uint_as_float(h2), __uint_as_float(h3));
    ((float4*)g_featL)[t] = make_float4(__uint_as_float(l0), __uint_as_float(l1),
                                        __uint_as_float(l2), __uint_as_float(l3));
}

// ---------------------------------------------------------------------------
// Sort chain: hist -> scan1 -> scan3(+cnt reset) -> scatter
// ---------------------------------------------------------------------------
__global__ void hist_kernel(const int* __restrict__ dst)
{
    int e = blockIdx.x * blockDim.x + threadIdx.x;
    if (e < N_EDGES) atomicAdd(&g_cnt[dst[e]], 1);
}

__global__ void __launch_bounds__(1024) scan1_kernel()
{
    __shared__ int wsum[32];
    const int tid = threadIdx.x, lane = tid & 31, wid = tid >> 5;
    const int idx = blockIdx.x * 1024 + tid;
    int v = (idx < N_NODES) ? g_cnt[idx] : 0;
    int x = v;
#pragma unroll
    for (int d = 1; d < 32; d <<= 1) {
        int y = __shfl_up_sync(0xffffffffu, x, d);
        if (lane >= d) x += y;
    }
    if (lane == 31) wsum[wid] = x;
    __syncthreads();
    if (tid < 32) {
        int w = wsum[tid];
#pragma unroll
        for (int d = 1; d < 32; d <<= 1) {
            int y = __shfl_up_sync(0xffffffffu, w, d);
            if (tid >= d) w += y;
        }
        wsum[tid] = w;
    }
    __syncthreads();
    int incl = x + (wid > 0 ? wsum[wid - 1] : 0);
    if (idx < N_NODES) g_scan[idx] = incl;
    if (tid == 1023)   g_bsum[blockIdx.x] = incl;
}

__global__ void __launch_bounds__(1024) scan3_kernel()
{
    __shared__ int s_pre;
    const int tid = threadIdx.x;
    if (tid < 32) {
        int v = (tid < blockIdx.x) ? g_bsum[tid] : 0;
#pragma unroll
        for (int d = 16; d > 0; d >>= 1) v += __shfl_xor_sync(0xffffffffu, v, d);
        if (tid == 0) s_pre = v;
    }
    __syncthreads();
    int idx = blockIdx.x * 1024 + tid;
    if (idx < N_NODES) {
        int c = g_cnt[idx];
        g_cur[idx] = g_scan[idx] + s_pre - c;
        g_cnt[idx] = 0;                        // self-restore for next replay
    }
}

__global__ void scatter_kernel(const int* __restrict__ dst,
                               const int* __restrict__ src,
                               const int* __restrict__ et)
{
    int e = blockIdx.x * blockDim.x + threadIdx.x;
    if (e < N_EDGES) {
        int d = dst[e];
        int pos = atomicAdd(&g_cur[d], 1);
        g_srcrt[pos] = (unsigned)src[e] | ((unsigned)et[e] << 16);
        g_dstS[pos]  = d;
    }
}

// ---------------------------------------------------------------------------
// proj_mma v3: r8-v1 main loop (proven), prologue = pure copy of pre-split
// planes. Tile 128 rows x 64 cols, 256 thr (8 warps, warp = m16 x n64).
// smem: AsHi/AsLo [128][68], BsHi/BsLo [64][72]  (~104 KB) -> 2 blocks/SM.
// ---------------------------------------------------------------------------
#define APAD 68
#define BPAD 72
#define PROJ_SMEM ((128 * APAD * 2 + 64 * BPAD * 2) * 4)

__global__ void __launch_bounds__(256) proj_mma_kernel(float* __restrict__ out)
{
    extern __shared__ uint32_t smem[];
    uint32_t* AsHi = smem;
    uint32_t* AsLo = AsHi + 128 * APAD;
    uint32_t* BsHi = AsLo + 128 * APAD;
    uint32_t* BsLo = BsHi + 64 * BPAD;

    const int tid = threadIdx.x;
    const int m0  = blockIdx.x * 128;
    const int c0  = blockIdx.y * 64;

    // ---- A tile copy (128 x 64), pre-split planes
#pragma unroll
    for (int i = 0; i < 8; i++) {
        int v = tid + i * 256;                 // 0..2047 float4 slots
        int row = v >> 4, c4 = (v & 15) * 4;
        int node = m0 + row;
        float4 h = make_float4(0.f, 0.f, 0.f, 0.f);
        float4 l = h;
        if (node < N_NODES) {
            h = *(const float4*)(g_featH + node * F + c4);
            l = *(const float4*)(g_featL + node * F + c4);
        }
        *(float4*)(AsHi + row * APAD + c4) = h;
        *(float4*)(AsLo + row * APAD + c4) = l;
    }
    // ---- B tile copy (64 k x 64 n), pre-split planes
#pragma unroll
    for (int i = 0; i < 4; i++) {
        int v = tid + i * 256;                 // 0..1023 float4 slots
        int k = v >> 4, n4 = (v & 15) * 4;
        float4 h = *(const float4*)(g_WH + k * WCOLS + c0 + n4);
        float4 l = *(const float4*)(g_WL + k * WCOLS + c0 + n4);
        *(float4*)(BsHi + k * BPAD + n4) = h;
        *(float4*)(BsLo + k * BPAD + n4) = l;
    }
    __syncthreads();

    const int wid  = tid >> 5;
    const int lane = tid & 31;
    const int gid  = lane >> 2;       // 0..7
    const int tig  = lane & 3;        // 0..3

    float d[8][4];
#pragma unroll
    for (int j = 0; j < 8; j++)
#pragma unroll
        for (int q = 0; q < 4; q++) d[j][q] = 0.f;

    const uint32_t* ahp = AsHi + (16 * wid + gid) * APAD + tig;
    const uint32_t* alp = AsLo + (16 * wid + gid) * APAD + tig;
    const uint32_t* bhp = BsHi + tig * BPAD + gid;
    const uint32_t* blp = BsLo + tig * BPAD + gid;

#pragma unroll
    for (int ks = 0; ks < 8; ks++) {
        uint32_t ah[4], al[4];
        ah[0] = ahp[ks * 8];
        ah[1] = ahp[8 * APAD + ks * 8];
        ah[2] = ahp[ks * 8 + 4];
        ah[3] = ahp[8 * APAD + ks * 8 + 4];
        al[0] = alp[ks * 8];
        al[1] = alp[8 * APAD + ks * 8];
        al[2] = alp[ks * 8 + 4];
        al[3] = alp[8 * APAD + ks * 8 + 4];
#pragma unroll
        for (int j = 0; j < 8; j++) {
            uint32_t bh[2], bl[2];
            bh[0] = bhp[ks * 8 * BPAD + 8 * j];
            bh[1] = bhp[(ks * 8 + 4) * BPAD + 8 * j];
            bl[0] = blp[ks * 8 * BPAD + 8 * j];
            bl[1] = blp[(ks * 8 + 4) * BPAD + 8 * j];
            mma_tf32(d[j], ah, bh);
            mma_tf32(d[j], al, bh);
            mma_tf32(d[j], ah, bl);
        }
    }

    // ---- epilogue: route to g_z / out / g_P
    const int r0 = m0 + 16 * wid + gid;
    const int cb = tig * 2;
#pragma unroll
    for (int j = 0; j < 8; j++) {
        int gc = c0 + 8 * j + cb;
        if (gc >= TOTC) continue;
#pragma unroll
        for (int half = 0; half < 2; half++) {
            int node = r0 + 8 * half;
            if (node >= N_NODES) continue;
            float x = d[j][2 * half], y = d[j][2 * half + 1];
            if (gc < 64) {
                *(float2*)(g_z + node * F + gc) = make_float2(x, y);
            } else if (gc < 384) {
                *(float2*)(out + node * OUTC + (gc - 64)) = make_float2(x, y);
            } else {
#pragma unroll
                for (int t = 0; t < 2; t++) {
                    int ix = gc - 384 + t;
                    int part = (ix >= 100) ? 8 : 0;
                    int pix  = (ix >= 100) ? ix - 100 : ix;
                    int rr = pix / 5, hh = pix % 5;
                    g_P[node * PSTRIDE + rr * 16 + part + hh] = t ? y : x;
                }
            }
        }
    }
}

// ---------------------------------------------------------------------------
// gather: edge-parallel aggregation over dst-sorted edges (r8, padded P).
// ---------------------------------------------------------------------------
__global__ void __launch_bounds__(256) gather_kernel(float* __restrict__ out)
{
    __shared__ float stage[8][328];
    const int w = threadIdx.x >> 5, lane = threadIdx.x & 31;
    const int gw = blockIdx.x * 8 + w;
    const int e0 = gw * CHUNK;
    if (e0 >= N_EDGES) return;
    const int e1 = min(e0 + CHUNK, N_EDGES);

    float acc[10];
#pragma unroll
    for (int q = 0; q < 10; q++) acc[q] = 0.f;

    int      d_n = g_dstS[e0];
    unsigned pk  = g_srcrt[e0];
    int s_n = pk & 0xFFFFu, r_n = pk >> 16;
    float2 zs_n = *(const float2*)(g_z + s_n * F + 2 * lane);
    const float* pp = g_P + s_n * PSTRIDE + r_n * 16;
    const float* qq = g_P + d_n * PSTRIDE + r_n * 16 + 8;
    float4 ps4_n = *(const float4*)pp;  float ps1_n = pp[4];
    float4 pd4_n = *(const float4*)qq;  float pd1_n = qq[4];
    int d_cur = d_n;

    for (int i = e0; i < e1; i++) {
        const int    d_c  = d_n;
        const float2 zs   = zs_n;
        const float4 ps4  = ps4_n, pd4 = pd4_n;
        const float  ps1  = ps1_n, pd1 = pd1_n;

        if (i + 1 < e1) {
            d_n = g_dstS[i + 1];
            pk  = g_srcrt[i + 1];
            int s2 = pk & 0xFFFFu, r2 = pk >> 16;
            zs_n = *(const float2*)(g_z + s2 * F + 2 * lane);
            const float* p2 = g_P + s2 * PSTRIDE + r2 * 16;
            const float* p3 = g_P + d_n * PSTRIDE + r2 * 16 + 8;
            ps4_n = *(const float4*)p2;  ps1_n = p2[4];
            pd4_n = *(const float4*)p3;  pd1_n = p3[4];
        }

        if (d_c != d_cur) {   // warp-uniform branch
#pragma unroll
            for (int h = 0; h < NHEADS; h++)
                *(float2*)&stage[w][h * F + 2 * lane] = make_float2(acc[2 * h], acc[2 * h + 1]);
            __syncwarp();
            float* ob = out + (long)d_cur * OUTC;
#pragma unroll
            for (int t = 0; t < 3; t++) {
                int cc = lane + 32 * t;
                if (cc < 80) {
                    float4 v = *(const float4*)&stage[w][cc * 4];
                    asm volatile("red.global.add.v4.f32 [%0], {%1, %2, %3, %4};"
                                 :: "l"(ob + 4 * cc), "f"(v.x), "f"(v.y), "f"(v.z), "f"(v.w)
                                 : "memory");
                }
            }
            __syncwarp();
#pragma unroll
            for (int q = 0; q < 10; q++) acc[q] = 0.f;
            d_cur = d_c;
        }

        float a0 = ps4.x + pd4.x;  a0 = a0 > 0.f ? a0 : 0.01f * a0;
        float a1 = ps4.y + pd4.y;  a1 = a1 > 0.f ? a1 : 0.01f * a1;
        float a2 = ps4.z + pd4.z;  a2 = a2 > 0.f ? a2 : 0.01f * a2;
        float a3 = ps4.w + pd4.w;  a3 = a3 > 0.f ? a3 : 0.01f * a3;
        float a4 = ps1   + pd1;    a4 = a4 > 0.f ? a4 : 0.01f * a4;
        acc[0] += a0 * zs.x;  acc[1] += a0 * zs.y;
        acc[2] += a1 * zs.x;  acc[3] += a1 * zs.y;
        acc[4] += a2 * zs.x;  acc[5] += a2 * zs.y;
        acc[6] += a3 * zs.x;  acc[7] += a3 * zs.y;
        acc[8] += a4 * zs.x;  acc[9] += a4 * zs.y;
    }

    // final flush
#pragma unroll
    for (int h = 0; h < NHEADS; h++)
        *(float2*)&stage[w][h * F + 2 * lane] = make_float2(acc[2 * h], acc[2 * h + 1]);
    __syncwarp();
    float* ob = out + (long)d_cur * OUTC;
#pragma unroll
    for (int t = 0; t < 3; t++) {
        int cc = lane + 32 * t;
        if (cc < 80) {
            float4 v = *(const float4*)&stage[w][cc * 4];
            asm volatile("red.global.add.v4.f32 [%0], {%1, %2, %3, %4};"
                         :: "l"(ob + 4 * cc), "f"(v.x), "f"(v.y), "f"(v.z), "f"(v.w)
                         : "memory");
        }
    }
}

// ---------------------------------------------------------------------------
extern "C" void kernel_launch(void* const* d_in, const int* in_sizes, int n_in,
                              void* d_out, int out_size)
{
    const float* feat      = (const float*)d_in[0];
    const int*   src       = (const int*)  d_in[1];
    const int*   dst       = (const int*)  d_in[2];
    const int*   etype     = (const int*)  d_in[3];
    const float* fc_w      = (const float*)d_in[4];
    const float* self_fc_w = (const float*)d_in[5];
    const float* aw        = (const float*)d_in[6];
    const float* w_comp    = (const float*)d_in[7];
    float* out = (float*)d_out;

    const int NB = (N_NODES + 1023) / 1024;   // 25

    cudaFuncSetAttribute(proj_mma_kernel,
                         cudaFuncAttributeMaxDynamicSharedMemorySize, PROJ_SMEM);

    attn_comp_kernel<<<NRELS, 320>>>(aw, w_comp, fc_w);                 // 1
    split_w_kernel<<<64, 640>>>(fc_w, self_fc_w);                       // 2
    split_feat_kernel<<<(N_NODES * F / 4 + 255) / 256, 256>>>(feat);    // 3
    proj_mma_kernel<<<dim3((N_NODES + 127) / 128, 10), 256, PROJ_SMEM>>>(out); // 4 (profiled)
    hist_kernel<<<(N_EDGES + 255) / 256, 256>>>(dst);                   // 5
    scan1_kernel<<<NB, 1024>>>();                                       // 6
    scan3_kernel<<<NB, 1024>>>();                                       // 7
    scatter_kernel<<<(N_EDGES + 255) / 256, 256>>>(dst, src, etype);    // 8
    gather_kernel<<<(N_EDGES / CHUNK + 7) / 8, 256>>>(out);             // 9
}

// round 11
// speedup vs baseline: 1.2565x; 1.0637x over previous
#include <cuda_runtime.h>
#include <cstdint>

#define N_NODES 25000
#define N_EDGES 320000
#define F       64
#define NHEADS  5
#define NRELS   20
#define NBASES  10
#define OUTC    320
#define PCOLS   200          // GEMM P-columns (compact): 100 s + 100 d
#define PSTRIDE 320          // padded per-node P row: 20 rels * 16
#define TOTC    584          // 64 z + 320 self_z + 200 P
#define WCOLS   640          // padded fused-W width
#define CHUNK   32

// ---------------- static device scratch ------------------------------------
__device__ float    g_z [N_NODES * F];          // 6.4 MB
__device__ float    g_W2[64 * PCOLS];
__device__ float    g_P [N_NODES * PSTRIDE];    // 32 MB padded
__device__ float    g_WH[64 * WCOLS];           // fused W hi plane
__device__ float    g_WL[64 * WCOLS];           // fused W lo plane
__device__ int      g_cnt [N_NODES];            // zero at load; self-restored by scan3
__device__ int      g_scan[N_NODES];
__device__ int      g_bsum[32];
__device__ int      g_cur [N_NODES];
__device__ unsigned g_srcrt[N_EDGES];           // src | rel<<16, sorted by dst
__device__ int      g_dstS [N_EDGES];           // dst, sorted

// ---------------- tf32 helpers ----------------------------------------------
__device__ __forceinline__ uint32_t f2tf32(float x) {
    uint32_t u;
    asm("cvt.rn.tf32.f32 %0, %1;" : "=r"(u) : "f"(x));
    return u;
}
__device__ __forceinline__ void tf32_split(float x, uint32_t& hi, uint32_t& lo) {
    hi = f2tf32(x);
    float r = x - __uint_as_float(hi);
    lo = f2tf32(r);
}
__device__ __forceinline__ void mma_tf32(float* d, const uint32_t* a, const uint32_t* b) {
    asm volatile("mma.sync.aligned.m16n8k8.row.col.f32.tf32.tf32.f32 "
                 "{%0,%1,%2,%3}, {%4,%5,%6,%7}, {%8,%9}, {%0,%1,%2,%3};"
                 : "+f"(d[0]), "+f"(d[1]), "+f"(d[2]), "+f"(d[3])
                 : "r"(a[0]), "r"(a[1]), "r"(a[2]), "r"(a[3]), "r"(b[0]), "r"(b[1]));
}

// ---------------------------------------------------------------------------
// K1: attention-weight composition.  One block per relation.
// ---------------------------------------------------------------------------
__global__ void __launch_bounds__(320) attn_comp_kernel(const float* __restrict__ aw,
                                                        const float* __restrict__ w_comp,
                                                        const float* __restrict__ fc_w)
{
    __shared__ float afc[128 * NHEADS];
    const int r = blockIdx.x, tid = threadIdx.x;

    if (tid < 128) {
        float acc[NHEADS] = {};
#pragma unroll
        for (int b = 0; b < NBASES; b++) {
            float wc = w_comp[r * NBASES + b];
#pragma unroll
            for (int h = 0; h < NHEADS; h++)
                acc[h] += wc * aw[(b * 128 + tid) * NHEADS + h];
        }
#pragma unroll
        for (int h = 0; h < NHEADS; h++) afc[tid * NHEADS + h] = acc[h];
    }
    __syncthreads();

    for (int o = tid; o < 640; o += 320) {
        int k = o / 10, c2 = o % 10, h = c2 % 5;
        const float* af = afc + (c2 >= 5 ? 64 * NHEADS : 0) + h;
        float sum = 0.f;
#pragma unroll
        for (int f = 0; f < 64; f++) sum += fc_w[k * 64 + f] * af[f * NHEADS];
        g_W2[k * PCOLS + (c2 >= 5 ? 100 : 0) + r * 5 + h] = sum;
    }
}

// ---------------------------------------------------------------------------
// K2: split fused weight matrix [fc_w | self_fc_w | W2 | 0pad] into tf32 planes.
// ---------------------------------------------------------------------------
__global__ void __launch_bounds__(640) split_w_kernel(const float* __restrict__ fc_w,
                                                      const float* __restrict__ self_fc_w)
{
    const int k = blockIdx.x, c = threadIdx.x;
    float x = 0.f;
    if (c < 64)        x = fc_w[k * 64 + c];
    else if (c < 384)  x = self_fc_w[k * 320 + (c - 64)];
    else if (c < TOTC) x = g_W2[k * PCOLS + (c - 384)];
    uint32_t hi, lo;
    tf32_split(x, hi, lo);
    g_WH[k * WCOLS + c] = __uint_as_float(hi);
    g_WL[k * WCOLS + c] = __uint_as_float(lo);
}

// ---------------------------------------------------------------------------
// Sort chain: hist -> scan1 -> scan3(+cnt reset) -> scatter
// ---------------------------------------------------------------------------
__global__ void hist_kernel(const int* __restrict__ dst)
{
    int e = blockIdx.x * blockDim.x + threadIdx.x;
    if (e < N_EDGES) atomicAdd(&g_cnt[dst[e]], 1);
}

__global__ void __launch_bounds__(1024) scan1_kernel()
{
    __shared__ int wsum[32];
    const int tid = threadIdx.x, lane = tid & 31, wid = tid >> 5;
    const int idx = blockIdx.x * 1024 + tid;
    int v = (idx < N_NODES) ? g_cnt[idx] : 0;
    int x = v;
#pragma unroll
    for (int d = 1; d < 32; d <<= 1) {
        int y = __shfl_up_sync(0xffffffffu, x, d);
        if (lane >= d) x += y;
    }
    if (lane == 31) wsum[wid] = x;
    __syncthreads();
    if (tid < 32) {
        int w = wsum[tid];
#pragma unroll
        for (int d = 1; d < 32; d <<= 1) {
            int y = __shfl_up_sync(0xffffffffu, w, d);
            if (tid >= d) w += y;
        }
        wsum[tid] = w;
    }
    __syncthreads();
    int incl = x + (wid > 0 ? wsum[wid - 1] : 0);
    if (idx < N_NODES) g_scan[idx] = incl;
    if (tid == 1023)   g_bsum[blockIdx.x] = incl;
}

__global__ void __launch_bounds__(1024) scan3_kernel()
{
    __shared__ int s_pre;
    const int tid = threadIdx.x;
    if (tid < 32) {
        int v = (tid < blockIdx.x) ? g_bsum[tid] : 0;
#pragma unroll
        for (int d = 16; d > 0; d >>= 1) v += __shfl_xor_sync(0xffffffffu, v, d);
        if (tid == 0) s_pre = v;
    }
    __syncthreads();
    int idx = blockIdx.x * 1024 + tid;
    if (idx < N_NODES) {
        int c = g_cnt[idx];
        g_cur[idx] = g_scan[idx] + s_pre - c;
        g_cnt[idx] = 0;                        // self-restore for next replay
    }
}

__global__ void scatter_kernel(const int* __restrict__ dst,
                               const int* __restrict__ src,
                               const int* __restrict__ et)
{
    int e = blockIdx.x * blockDim.x + threadIdx.x;
    if (e < N_EDGES) {
        int d = dst[e];
        int pos = atomicAdd(&g_cur[d], 1);
        g_srcrt[pos] = (unsigned)src[e] | ((unsigned)et[e] << 16);
        g_dstS[pos]  = d;
    }
}

// ---------------------------------------------------------------------------
// proj_mma v4: collapsed grid — block owns 64 rows, loops over 10 col-chunks.
// A split in-kernel ONCE per block; B chunks copied from pre-split planes.
// 256 thr (8 warps): warp = (row-group wid&3) x (col-half wid>>2) = m16 x n32.
// smem: AsHi/AsLo [64][68] + BsHi/BsLo [64][72] = 71.7 KB -> 3 blocks/SM.
// ---------------------------------------------------------------------------
#define APAD 68
#define BPAD 72
#define PROJ_SMEM ((64 * APAD * 2 + 64 * BPAD * 2) * 4)

__global__ void __launch_bounds__(256) proj_mma_kernel(const float* __restrict__ feat,
                                                       float* __restrict__ out)
{
    extern __shared__ uint32_t smem[];
    uint32_t* AsHi = smem;
    uint32_t* AsLo = AsHi + 64 * APAD;
    uint32_t* BsHi = AsLo + 64 * APAD;
    uint32_t* BsLo = BsHi + 64 * BPAD;

    const int tid = threadIdx.x;
    const int m0  = blockIdx.x * 64;

    // ---- A tile (64 x 64): load feat + tf32-split, once per block
#pragma unroll
    for (int i = 0; i < 4; i++) {
        int v = tid + i * 256;                 // 0..1023 float4 slots
        int row = v >> 4, k4 = (v & 15) * 4;
        int node = m0 + row;
        float4 a = make_float4(0.f, 0.f, 0.f, 0.f);
        if (node < N_NODES) a = *(const float4*)(feat + node * F + k4);
        float av[4] = {a.x, a.y, a.z, a.w};
        uint32_t* hp = AsHi + row * APAD + k4;
        uint32_t* lp = AsLo + row * APAD + k4;
#pragma unroll
        for (int e = 0; e < 4; e++) tf32_split(av[e], hp[e], lp[e]);
    }

    const int wid  = tid >> 5;
    const int lane = tid & 31;
    const int gid  = lane >> 2;       // 0..7
    const int tig  = lane & 3;        // 0..3
    const int wrow = wid & 3;         // row group
    const int wcol = (wid >> 2) * 32; // col half within chunk

    const uint32_t* ahp = AsHi + (16 * wrow + gid) * APAD + tig;
    const uint32_t* alp = AsLo + (16 * wrow + gid) * APAD + tig;
    const uint32_t* bhp = BsHi + tig * BPAD + wcol + gid;
    const uint32_t* blp = BsLo + tig * BPAD + wcol + gid;
    const int r0 = m0 + 16 * wrow + gid;

#pragma unroll 1
    for (int c0 = 0; c0 < WCOLS; c0 += 64) {
        __syncthreads();   // prior chunk's MMA readers done (also covers A split @c0=0)
        // ---- B chunk copy (64 k x 64 n), pre-split planes
#pragma unroll
        for (int i = 0; i < 4; i++) {
            int v = tid + i * 256;
            int k = v >> 4, n4 = (v & 15) * 4;
            float4 h = *(const float4*)(g_WH + k * WCOLS + c0 + n4);
            float4 l = *(const float4*)(g_WL + k * WCOLS + c0 + n4);
            *(float4*)(BsHi + k * BPAD + n4) = h;
            *(float4*)(BsLo + k * BPAD + n4) = l;
        }
        __syncthreads();

        float d[4][4];
#pragma unroll
        for (int j = 0; j < 4; j++)
#pragma unroll
            for (int q = 0; q < 4; q++) d[j][q] = 0.f;

#pragma unroll
        for (int ks = 0; ks < 8; ks++) {
            uint32_t ah[4], al[4];
            ah[0] = ahp[ks * 8];
            ah[1] = ahp[8 * APAD + ks * 8];
            ah[2] = ahp[ks * 8 + 4];
            ah[3] = ahp[8 * APAD + ks * 8 + 4];
            al[0] = alp[ks * 8];
            al[1] = alp[8 * APAD + ks * 8];
            al[2] = alp[ks * 8 + 4];
            al[3] = alp[8 * APAD + ks * 8 + 4];
#pragma unroll
            for (int j = 0; j < 4; j++) {
                uint32_t bh[2], bl[2];
                bh[0] = bhp[ks * 8 * BPAD + 8 * j];
                bh[1] = bhp[(ks * 8 + 4) * BPAD + 8 * j];
                bl[0] = blp[ks * 8 * BPAD + 8 * j];
                bl[1] = blp[(ks * 8 + 4) * BPAD + 8 * j];
                mma_tf32(d[j], ah, bh);
                mma_tf32(d[j], al, bh);
                mma_tf32(d[j], ah, bl);
            }
        }

        // ---- epilogue for this chunk: route to g_z / out / g_P
        const int cb = tig * 2;
#pragma unroll
        for (int j = 0; j < 4; j++) {
            int gc = c0 + wcol + 8 * j + cb;
            if (gc >= TOTC) continue;
#pragma unroll
            for (int half = 0; half < 2; half++) {
                int node = r0 + 8 * half;
                if (node >= N_NODES) continue;
                float x = d[j][2 * half], y = d[j][2 * half + 1];
                if (gc < 64) {
                    *(float2*)(g_z + node * F + gc) = make_float2(x, y);
                } else if (gc < 384) {
                    *(float2*)(out + node * OUTC + (gc - 64)) = make_float2(x, y);
                } else {
#pragma unroll
                    for (int t = 0; t < 2; t++) {
                        int ix = gc - 384 + t;
                        int part = (ix >= 100) ? 8 : 0;
                        int pix  = (ix >= 100) ? ix - 100 : ix;
                        int rr = pix / 5, hh = pix % 5;
                        g_P[node * PSTRIDE + rr * 16 + part + hh] = t ? y : x;
                    }
                }
            }
        }
    }
}

// ---------------------------------------------------------------------------
// gather: edge-parallel aggregation over dst-sorted edges (r8, padded P).
// ---------------------------------------------------------------------------
__global__ void __launch_bounds__(256) gather_kernel(float* __restrict__ out)
{
    __shared__ float stage[8][328];
    const int w = threadIdx.x >> 5, lane = threadIdx.x & 31;
    const int gw = blockIdx.x * 8 + w;
    const int e0 = gw * CHUNK;
    if (e0 >= N_EDGES) return;
    const int e1 = min(e0 + CHUNK, N_EDGES);

    float acc[10];
#pragma unroll
    for (int q = 0; q < 10; q++) acc[q] = 0.f;

    int      d_n = g_dstS[e0];
    unsigned pk  = g_srcrt[e0];
    int s_n = pk & 0xFFFFu, r_n = pk >> 16;
    float2 zs_n = *(const float2*)(g_z + s_n * F + 2 * lane);
    const float* pp = g_P + s_n * PSTRIDE + r_n * 16;
    const float* qq = g_P + d_n * PSTRIDE + r_n * 16 + 8;
    float4 ps4_n = *(const float4*)pp;  float ps1_n = pp[4];
    float4 pd4_n = *(const float4*)qq;  float pd1_n = qq[4];
    int d_cur = d_n;

    for (int i = e0; i < e1; i++) {
        const int    d_c  = d_n;
        const float2 zs   = zs_n;
        const float4 ps4  = ps4_n, pd4 = pd4_n;
        const float  ps1  = ps1_n, pd1 = pd1_n;

        if (i + 1 < e1) {
            d_n = g_dstS[i + 1];
            pk  = g_srcrt[i + 1];
            int s2 = pk & 0xFFFFu, r2 = pk >> 16;
            zs_n = *(const float2*)(g_z + s2 * F + 2 * lane);
            const float* p2 = g_P + s2 * PSTRIDE + r2 * 16;
            const float* p3 = g_P + d_n * PSTRIDE + r2 * 16 + 8;
            ps4_n = *(const float4*)p2;  ps1_n = p2[4];
            pd4_n = *(const float4*)p3;  pd1_n = p3[4];
        }

        if (d_c != d_cur) {   // warp-uniform branch
#pragma unroll
            for (int h = 0; h < NHEADS; h++)
                *(float2*)&stage[w][h * F + 2 * lane] = make_float2(acc[2 * h], acc[2 * h + 1]);
            __syncwarp();
            float* ob = out + (long)d_cur * OUTC;
#pragma unroll
            for (int t = 0; t < 3; t++) {
                int cc = lane + 32 * t;
                if (cc < 80) {
                    float4 v = *(const float4*)&stage[w][cc * 4];
                    asm volatile("red.global.add.v4.f32 [%0], {%1, %2, %3, %4};"
                                 :: "l"(ob + 4 * cc), "f"(v.x), "f"(v.y), "f"(v.z), "f"(v.w)
                                 : "memory");
                }
            }
            __syncwarp();
#pragma unroll
            for (int q = 0; q < 10; q++) acc[q] = 0.f;
            d_cur = d_c;
        }

        float a0 = ps4.x + pd4.x;  a0 = a0 > 0.f ? a0 : 0.01f * a0;
        float a1 = ps4.y + pd4.y;  a1 = a1 > 0.f ? a1 : 0.01f * a1;
        float a2 = ps4.z + pd4.z;  a2 = a2 > 0.f ? a2 : 0.01f * a2;
        float a3 = ps4.w + pd4.w;  a3 = a3 > 0.f ? a3 : 0.01f * a3;
        float a4 = ps1   + pd1;    a4 = a4 > 0.f ? a4 : 0.01f * a4;
        acc[0] += a0 * zs.x;  acc[1] += a0 * zs.y;
        acc[2] += a1 * zs.x;  acc[3] += a1 * zs.y;
        acc[4] += a2 * zs.x;  acc[5] += a2 * zs.y;
        acc[6] += a3 * zs.x;  acc[7] += a3 * zs.y;
        acc[8] += a4 * zs.x;  acc[9] += a4 * zs.y;
    }

    // final flush
#pragma unroll
    for (int h = 0; h < NHEADS; h++)
        *(float2*)&stage[w][h * F + 2 * lane] = make_float2(acc[2 * h], acc[2 * h + 1]);
    __syncwarp();
    float* ob = out + (long)d_cur * OUTC;
#pragma unroll
    for (int t = 0; t < 3; t++) {
        int cc = lane + 32 * t;
        if (cc < 80) {
            float4 v = *(const float4*)&stage[w][cc * 4];
            asm volatile("red.global.add.v4.f32 [%0], {%1, %2, %3, %4};"
                         :: "l"(ob + 4 * cc), "f"(v.x), "f"(v.y), "f"(v.z), "f"(v.w)
                         : "memory");
        }
    }
}

// ---------------------------------------------------------------------------
extern "C" void kernel_launch(void* const* d_in, const int* in_sizes, int n_in,
                              void* d_out, int out_size)
{
    const float* feat      = (const float*)d_in[0];
    const int*   src       = (const int*)  d_in[1];
    const int*   dst       = (const int*)  d_in[2];
    const int*   etype     = (const int*)  d_in[3];
    const float* fc_w      = (const float*)d_in[4];
    const float* self_fc_w = (const float*)d_in[5];
    const float* aw        = (const float*)d_in[6];
    const float* w_comp    = (const float*)d_in[7];
    float* out = (float*)d_out;

    const int NB = (N_NODES + 1023) / 1024;   // 25

    cudaFuncSetAttribute(proj_mma_kernel,
                         cudaFuncAttributeMaxDynamicSharedMemorySize, PROJ_SMEM);

    attn_comp_kernel<<<NRELS, 320>>>(aw, w_comp, fc_w);                 // 1
    split_w_kernel<<<64, 640>>>(fc_w, self_fc_w);                       // 2
    hist_kernel<<<(N_EDGES + 255) / 256, 256>>>(dst);                   // 3
    proj_mma_kernel<<<(N_NODES + 63) / 64, 256, PROJ_SMEM>>>(feat, out); // 4 (profiled)
    scan1_kernel<<<NB, 1024>>>();                                       // 5
    scan3_kernel<<<NB, 1024>>>();                                       // 6
    scatter_kernel<<<(N_EDGES + 255) / 256, 256>>>(dst, src, etype);    // 7
    gather_kernel<<<(N_EDGES / CHUNK + 7) / 8, 256>>>(out);             // 8
}

// round 12
// speedup vs baseline: 1.3146x; 1.0462x over previous
#include <cuda_runtime.h>
#include <cstdint>

#define N_NODES 25000
#define N_EDGES 320000
#define F       64
#define NHEADS  5
#define NRELS   20
#define NBASES  10
#define OUTC    320
#define PCOLS   200          // GEMM P-columns (compact): 100 s + 100 d
#define PSTRIDE 320          // padded per-node P row: 20 rels * 16
#define TOTC    584          // 64 z + 320 self_z + 200 P
#define WCOLS   640          // padded fused-W width
#define CHUNK   32

// ---------------- static device scratch ------------------------------------
__device__ float    g_z [N_NODES * F];          // 6.4 MB
__device__ float    g_W2[64 * PCOLS];
__device__ float    g_P [N_NODES * PSTRIDE];    // 32 MB padded
__device__ float    g_WH[64 * WCOLS];           // fused W hi plane
__device__ float    g_WL[64 * WCOLS];           // fused W lo plane
__device__ int      g_cnt [N_NODES];            // zero at load; self-restored by scan3
__device__ int      g_scan[N_NODES];
__device__ int      g_bsum[32];
__device__ int      g_cur [N_NODES];
__device__ unsigned g_srcrt[N_EDGES];           // src | rel<<16, sorted by dst
__device__ int      g_dstS [N_EDGES];           // dst, sorted

// ---------------- tf32 helpers ----------------------------------------------
__device__ __forceinline__ uint32_t f2tf32(float x) {
    uint32_t u;
    asm("cvt.rn.tf32.f32 %0, %1;" : "=r"(u) : "f"(x));
    return u;
}
__device__ __forceinline__ void tf32_split(float x, uint32_t& hi, uint32_t& lo) {
    hi = f2tf32(x);
    float r = x - __uint_as_float(hi);
    lo = f2tf32(r);
}
__device__ __forceinline__ void mma_tf32(float* d, const uint32_t* a, const uint32_t* b) {
    asm volatile("mma.sync.aligned.m16n8k8.row.col.f32.tf32.tf32.f32 "
                 "{%0,%1,%2,%3}, {%4,%5,%6,%7}, {%8,%9}, {%0,%1,%2,%3};"
                 : "+f"(d[0]), "+f"(d[1]), "+f"(d[2]), "+f"(d[3])
                 : "r"(a[0]), "r"(a[1]), "r"(a[2]), "r"(a[3]), "r"(b[0]), "r"(b[1]));
}

// ---------------------------------------------------------------------------
// K1: attention-weight composition.  One block per relation.
// ---------------------------------------------------------------------------
__global__ void __launch_bounds__(320) attn_comp_kernel(const float* __restrict__ aw,
                                                        const float* __restrict__ w_comp,
                                                        const float* __restrict__ fc_w)
{
    __shared__ float afc[128 * NHEADS];
    const int r = blockIdx.x, tid = threadIdx.x;

    if (tid < 128) {
        float acc[NHEADS] = {};
#pragma unroll
        for (int b = 0; b < NBASES; b++) {
            float wc = w_comp[r * NBASES + b];
#pragma unroll
            for (int h = 0; h < NHEADS; h++)
                acc[h] += wc * aw[(b * 128 + tid) * NHEADS + h];
        }
#pragma unroll
        for (int h = 0; h < NHEADS; h++) afc[tid * NHEADS + h] = acc[h];
    }
    __syncthreads();

    for (int o = tid; o < 640; o += 320) {
        int k = o / 10, c2 = o % 10, h = c2 % 5;
        const float* af = afc + (c2 >= 5 ? 64 * NHEADS : 0) + h;
        float sum = 0.f;
#pragma unroll
        for (int f = 0; f < 64; f++) sum += fc_w[k * 64 + f] * af[f * NHEADS];
        g_W2[k * PCOLS + (c2 >= 5 ? 100 : 0) + r * 5 + h] = sum;
    }
}

// ---------------------------------------------------------------------------
// K2: split fused weight matrix [fc_w | self_fc_w | W2 | 0pad] into tf32 planes.
// ---------------------------------------------------------------------------
__global__ void __launch_bounds__(640) split_w_kernel(const float* __restrict__ fc_w,
                                                      const float* __restrict__ self_fc_w)
{
    const int k = blockIdx.x, c = threadIdx.x;
    float x = 0.f;
    if (c < 64)        x = fc_w[k * 64 + c];
    else if (c < 384)  x = self_fc_w[k * 320 + (c - 64)];
    else if (c < TOTC) x = g_W2[k * PCOLS + (c - 384)];
    uint32_t hi, lo;
    tf32_split(x, hi, lo);
    g_WH[k * WCOLS + c] = __uint_as_float(hi);
    g_WL[k * WCOLS + c] = __uint_as_float(lo);
}

// ---------------------------------------------------------------------------
// Sort chain: hist -> scan1 -> scan3(+cnt reset) -> scatter
// ---------------------------------------------------------------------------
__global__ void hist_kernel(const int* __restrict__ dst)
{
    int e = blockIdx.x * blockDim.x + threadIdx.x;
    if (e < N_EDGES) atomicAdd(&g_cnt[dst[e]], 1);
}

__global__ void __launch_bounds__(1024) scan1_kernel()
{
    __shared__ int wsum[32];
    const int tid = threadIdx.x, lane = tid & 31, wid = tid >> 5;
    const int idx = blockIdx.x * 1024 + tid;
    int v = (idx < N_NODES) ? g_cnt[idx] : 0;
    int x = v;
#pragma unroll
    for (int d = 1; d < 32; d <<= 1) {
        int y = __shfl_up_sync(0xffffffffu, x, d);
        if (lane >= d) x += y;
    }
    if (lane == 31) wsum[wid] = x;
    __syncthreads();
    if (tid < 32) {
        int w = wsum[tid];
#pragma unroll
        for (int d = 1; d < 32; d <<= 1) {
            int y = __shfl_up_sync(0xffffffffu, w, d);
            if (tid >= d) w += y;
        }
        wsum[tid] = w;
    }
    __syncthreads();
    int incl = x + (wid > 0 ? wsum[wid - 1] : 0);
    if (idx < N_NODES) g_scan[idx] = incl;
    if (tid == 1023)   g_bsum[blockIdx.x] = incl;
}

__global__ void __launch_bounds__(1024) scan3_kernel()
{
    __shared__ int s_pre;
    const int tid = threadIdx.x;
    if (tid < 32) {
        int v = (tid < blockIdx.x) ? g_bsum[tid] : 0;
#pragma unroll
        for (int d = 16; d > 0; d >>= 1) v += __shfl_xor_sync(0xffffffffu, v, d);
        if (tid == 0) s_pre = v;
    }
    __syncthreads();
    int idx = blockIdx.x * 1024 + tid;
    if (idx < N_NODES) {
        int c = g_cnt[idx];
        g_cur[idx] = g_scan[idx] + s_pre - c;
        g_cnt[idx] = 0;                        // self-restore for next replay
    }
}

__global__ void scatter_kernel(const int* __restrict__ dst,
                               const int* __restrict__ src,
                               const int* __restrict__ et)
{
    int e = blockIdx.x * blockDim.x + threadIdx.x;
    if (e < N_EDGES) {
        int d = dst[e];
        int pos = atomicAdd(&g_cur[d], 1);
        g_srcrt[pos] = (unsigned)src[e] | ((unsigned)et[e] << 16);
        g_dstS[pos]  = d;
    }
}

// ---------------------------------------------------------------------------
// proj_mma v5: block owns 64 rows, loops over 10 col-chunks.
// B chunks double-buffered through REGISTERS: next chunk's planes prefetched
// (LDG) right after the current smem store, hiding L2 latency under MMAs.
// 256 thr (8 warps): warp = (row-group wid&3) x (col-half wid>>2) = m16 x n32.
// smem: AsHi/AsLo [64][68] + BsHi/BsLo [64][72] = 71.7 KB -> 3 blocks/SM.
// ---------------------------------------------------------------------------
#define APAD 68
#define BPAD 72
#define PROJ_SMEM ((64 * APAD * 2 + 64 * BPAD * 2) * 4)

__global__ void __launch_bounds__(256, 3) proj_mma_kernel(const float* __restrict__ feat,
                                                          float* __restrict__ out)
{
    extern __shared__ uint32_t smem[];
    uint32_t* AsHi = smem;
    uint32_t* AsLo = AsHi + 64 * APAD;
    uint32_t* BsHi = AsLo + 64 * APAD;
    uint32_t* BsLo = BsHi + 64 * BPAD;

    const int tid = threadIdx.x;
    const int m0  = blockIdx.x * 64;

    // copy-loop indices (fixed per thread)
    const int ck0 = tid >> 4;              // k row for i=0 slot
    const int cn4 = (tid & 15) * 4;        // n4 within chunk

    // ---- prefetch chunk 0 B planes into registers
    float4 hbuf[4], lbuf[4];
#pragma unroll
    for (int i = 0; i < 4; i++) {
        int k = ck0 + i * 16;
        hbuf[i] = *(const float4*)(g_WH + k * WCOLS + cn4);
        lbuf[i] = *(const float4*)(g_WL + k * WCOLS + cn4);
    }

    // ---- A tile (64 x 64): load feat + tf32-split, once per block
#pragma unroll
    for (int i = 0; i < 4; i++) {
        int v = tid + i * 256;                 // 0..1023 float4 slots
        int row = v >> 4, k4 = (v & 15) * 4;
        int node = m0 + row;
        float4 a = make_float4(0.f, 0.f, 0.f, 0.f);
        if (node < N_NODES) a = *(const float4*)(feat + node * F + k4);
        float av[4] = {a.x, a.y, a.z, a.w};
        uint32_t* hp = AsHi + row * APAD + k4;
        uint32_t* lp = AsLo + row * APAD + k4;
#pragma unroll
        for (int e = 0; e < 4; e++) tf32_split(av[e], hp[e], lp[e]);
    }

    const int wid  = tid >> 5;
    const int lane = tid & 31;
    const int gid  = lane >> 2;       // 0..7
    const int tig  = lane & 3;        // 0..3
    const int wrow = wid & 3;         // row group
    const int wcol = (wid >> 2) * 32; // col half within chunk

    const uint32_t* ahp = AsHi + (16 * wrow + gid) * APAD + tig;
    const uint32_t* alp = AsLo + (16 * wrow + gid) * APAD + tig;
    const uint32_t* bhp = BsHi + tig * BPAD + wcol + gid;
    const uint32_t* blp = BsLo + tig * BPAD + wcol + gid;
    const int r0 = m0 + 16 * wrow + gid;

#pragma unroll 1
    for (int c0 = 0; c0 < WCOLS; c0 += 64) {
        __syncthreads();   // prev chunk's MMA readers done (also covers A split @c0=0)
        // ---- store staged B regs -> smem
#pragma unroll
        for (int i = 0; i < 4; i++) {
            int k = ck0 + i * 16;
            *(float4*)(BsHi + k * BPAD + cn4) = hbuf[i];
            *(float4*)(BsLo + k * BPAD + cn4) = lbuf[i];
        }
        __syncthreads();
        // ---- prefetch next chunk's B planes (overlaps MMA below)
        if (c0 + 64 < WCOLS) {
#pragma unroll
            for (int i = 0; i < 4; i++) {
                int k = ck0 + i * 16;
                hbuf[i] = *(const float4*)(g_WH + k * WCOLS + c0 + 64 + cn4);
                lbuf[i] = *(const float4*)(g_WL + k * WCOLS + c0 + 64 + cn4);
            }
        }

        float d[4][4];
#pragma unroll
        for (int j = 0; j < 4; j++)
#pragma unroll
            for (int q = 0; q < 4; q++) d[j][q] = 0.f;

#pragma unroll
        for (int ks = 0; ks < 8; ks++) {
            uint32_t ah[4], al[4];
            ah[0] = ahp[ks * 8];
            ah[1] = ahp[8 * APAD + ks * 8];
            ah[2] = ahp[ks * 8 + 4];
            ah[3] = ahp[8 * APAD + ks * 8 + 4];
            al[0] = alp[ks * 8];
            al[1] = alp[8 * APAD + ks * 8];
            al[2] = alp[ks * 8 + 4];
            al[3] = alp[8 * APAD + ks * 8 + 4];
#pragma unroll
            for (int j = 0; j < 4; j++) {
                uint32_t bh[2], bl[2];
                bh[0] = bhp[ks * 8 * BPAD + 8 * j];
                bh[1] = bhp[(ks * 8 + 4) * BPAD + 8 * j];
                bl[0] = blp[ks * 8 * BPAD + 8 * j];
                bl[1] = blp[(ks * 8 + 4) * BPAD + 8 * j];
                mma_tf32(d[j], ah, bh);
                mma_tf32(d[j], al, bh);
                mma_tf32(d[j], ah, bl);
            }
        }

        // ---- epilogue for this chunk: route to g_z / out / g_P
        const int cb = tig * 2;
#pragma unroll
        for (int j = 0; j < 4; j++) {
            int gc = c0 + wcol + 8 * j + cb;
            if (gc >= TOTC) continue;
#pragma unroll
            for (int half = 0; half < 2; half++) {
                int node = r0 + 8 * half;
                if (node >= N_NODES) continue;
                float x = d[j][2 * half], y = d[j][2 * half + 1];
                if (gc < 64) {
                    *(float2*)(g_z + node * F + gc) = make_float2(x, y);
                } else if (gc < 384) {
                    *(float2*)(out + node * OUTC + (gc - 64)) = make_float2(x, y);
                } else {
#pragma unroll
                    for (int t = 0; t < 2; t++) {
                        int ix = gc - 384 + t;
                        int part = (ix >= 100) ? 8 : 0;
                        int pix  = (ix >= 100) ? ix - 100 : ix;
                        int rr = pix / 5, hh = pix % 5;
                        g_P[node * PSTRIDE + rr * 16 + part + hh] = t ? y : x;
                    }
                }
            }
        }
    }
}

// ---------------------------------------------------------------------------
// gather: edge-parallel aggregation over dst-sorted edges (r8, padded P).
// ---------------------------------------------------------------------------
__global__ void __launch_bounds__(256) gather_kernel(float* __restrict__ out)
{
    __shared__ float stage[8][328];
    const int w = threadIdx.x >> 5, lane = threadIdx.x & 31;
    const int gw = blockIdx.x * 8 + w;
    const int e0 = gw * CHUNK;
    if (e0 >= N_EDGES) return;
    const int e1 = min(e0 + CHUNK, N_EDGES);

    float acc[10];
#pragma unroll
    for (int q = 0; q < 10; q++) acc[q] = 0.f;

    int      d_n = g_dstS[e0];
    unsigned pk  = g_srcrt[e0];
    int s_n = pk & 0xFFFFu, r_n = pk >> 16;
    float2 zs_n = *(const float2*)(g_z + s_n * F + 2 * lane);
    const float* pp = g_P + s_n * PSTRIDE + r_n * 16;
    const float* qq = g_P + d_n * PSTRIDE + r_n * 16 + 8;
    float4 ps4_n = *(const float4*)pp;  float ps1_n = pp[4];
    float4 pd4_n = *(const float4*)qq;  float pd1_n = qq[4];
    int d_cur = d_n;

    for (int i = e0; i < e1; i++) {
        const int    d_c  = d_n;
        const float2 zs   = zs_n;
        const float4 ps4  = ps4_n, pd4 = pd4_n;
        const float  ps1  = ps1_n, pd1 = pd1_n;

        if (i + 1 < e1) {
            d_n = g_dstS[i + 1];
            pk  = g_srcrt[i + 1];
            int s2 = pk & 0xFFFFu, r2 = pk >> 16;
            zs_n = *(const float2*)(g_z + s2 * F + 2 * lane);
            const float* p2 = g_P + s2 * PSTRIDE + r2 * 16;
            const float* p3 = g_P + d_n * PSTRIDE + r2 * 16 + 8;
            ps4_n = *(const float4*)p2;  ps1_n = p2[4];
            pd4_n = *(const float4*)p3;  pd1_n = p3[4];
        }

        if (d_c != d_cur) {   // warp-uniform branch
#pragma unroll
            for (int h = 0; h < NHEADS; h++)
                *(float2*)&stage[w][h * F + 2 * lane] = make_float2(acc[2 * h], acc[2 * h + 1]);
            __syncwarp();
            float* ob = out + (long)d_cur * OUTC;
#pragma unroll
            for (int t = 0; t < 3; t++) {
                int cc = lane + 32 * t;
                if (cc < 80) {
                    float4 v = *(const float4*)&stage[w][cc * 4];
                    asm volatile("red.global.add.v4.f32 [%0], {%1, %2, %3, %4};"
                                 :: "l"(ob + 4 * cc), "f"(v.x), "f"(v.y), "f"(v.z), "f"(v.w)
                                 : "memory");
                }
            }
            __syncwarp();
#pragma unroll
            for (int q = 0; q < 10; q++) acc[q] = 0.f;
            d_cur = d_c;
        }

        float a0 = ps4.x + pd4.x;  a0 = a0 > 0.f ? a0 : 0.01f * a0;
        float a1 = ps4.y + pd4.y;  a1 = a1 > 0.f ? a1 : 0.01f * a1;
        float a2 = ps4.z + pd4.z;  a2 = a2 > 0.f ? a2 : 0.01f * a2;
        float a3 = ps4.w + pd4.w;  a3 = a3 > 0.f ? a3 : 0.01f * a3;
        float a4 = ps1   + pd1;    a4 = a4 > 0.f ? a4 : 0.01f * a4;
        acc[0] += a0 * zs.x;  acc[1] += a0 * zs.y;
        acc[2] += a1 * zs.x;  acc[3] += a1 * zs.y;
        acc[4] += a2 * zs.x;  acc[5] += a2 * zs.y;
        acc[6] += a3 * zs.x;  acc[7] += a3 * zs.y;
        acc[8] += a4 * zs.x;  acc[9] += a4 * zs.y;
    }

    // final flush
#pragma unroll
    for (int h = 0; h < NHEADS; h++)
        *(float2*)&stage[w][h * F + 2 * lane] = make_float2(acc[2 * h], acc[2 * h + 1]);
    __syncwarp();
    float* ob = out + (long)d_cur * OUTC;
#pragma unroll
    for (int t = 0; t < 3; t++) {
        int cc = lane + 32 * t;
        if (cc < 80) {
            float4 v = *(const float4*)&stage[w][cc * 4];
            asm volatile("red.global.add.v4.f32 [%0], {%1, %2, %3, %4};"
                         :: "l"(ob + 4 * cc), "f"(v.x), "f"(v.y), "f"(v.z), "f"(v.w)
                         : "memory");
        }
    }
}

// ---------------------------------------------------------------------------
extern "C" void kernel_launch(void* const* d_in, const int* in_sizes, int n_in,
                              void* d_out, int out_size)
{
    const float* feat      = (const float*)d_in[0];
    const int*   src       = (const int*)  d_in[1];
    const int*   dst       = (const int*)  d_in[2];
    const int*   etype     = (const int*)  d_in[3];
    const float* fc_w      = (const float*)d_in[4];
    const float* self_fc_w = (const float*)d_in[5];
    const float* aw        = (const float*)d_in[6];
    const float* w_comp    = (const float*)d_in[7];
    float* out = (float*)d_out;

    const int NB = (N_NODES + 1023) / 1024;   // 25

    static cudaStream_t s_side = nullptr;
    static cudaEvent_t  ev_fork = nullptr, ev_sort = nullptr;
    if (s_side == nullptr) {
        cudaStreamCreateWithFlags(&s_side, cudaStreamNonBlocking);
        cudaEventCreateWithFlags(&ev_fork, cudaEventDisableTiming);
        cudaEventCreateWithFlags(&ev_sort, cudaEventDisableTiming);
        cudaFuncSetAttribute(proj_mma_kernel,
                             cudaFuncAttributeMaxDynamicSharedMemorySize, PROJ_SMEM);
    }

    // ---- fork: sort chain on side stream (independent of weights/proj)
    cudaEventRecord(ev_fork, 0);
    cudaStreamWaitEvent(s_side, ev_fork, 0);
    hist_kernel<<<(N_EDGES + 255) / 256, 256, 0, s_side>>>(dst);
    scan1_kernel<<<NB, 1024, 0, s_side>>>();
    scan3_kernel<<<NB, 1024, 0, s_side>>>();
    scatter_kernel<<<(N_EDGES + 255) / 256, 256, 0, s_side>>>(dst, src, etype);
    cudaEventRecord(ev_sort, s_side);

    // ---- main stream: weights -> projection GEMM
    attn_comp_kernel<<<NRELS, 320>>>(aw, w_comp, fc_w);
    split_w_kernel<<<64, 640>>>(fc_w, self_fc_w);
    proj_mma_kernel<<<(N_NODES + 63) / 64, 256, PROJ_SMEM>>>(feat, out);

    // ---- join, then gather
    cudaStreamWaitEvent(0, ev_sort, 0);
    gather_kernel<<<(N_EDGES / CHUNK + 7) / 8, 256>>>(out);
}

// round 13
// speedup vs baseline: 1.5913x; 1.2105x over previous
#include <cuda_runtime.h>
#include <cstdint>

#define N_NODES 25000
#define N_EDGES 320000
#define F       64
#define NHEADS  5
#define NRELS   20
#define NBASES  10
#define OUTC    320
#define PCOLS   200          // GEMM P-columns (compact): 100 s + 100 d
#define PSTRIDE 320          // padded per-node P row: 20 rels * 16
#define TOTC    584          // 64 z + 320 self_z + 200 P
#define WCOLS   640          // padded fused-W width
#define CHUNK   32
#define KW      32           // k-words per column (64 k / 2 per word)
#define SSTR    36           // smem row stride (words), conflict-free

// ---------------- static device scratch ------------------------------------
__device__ float    g_z [N_NODES * F];          // 6.4 MB
__device__ float    g_W2[64 * PCOLS];
__device__ float    g_P [N_NODES * PSTRIDE];    // 32 MB padded
__device__ uint32_t g_WbH[WCOLS * KW];          // fused W bf16x2 hi plane, [c][kw]
__device__ uint32_t g_WbL[WCOLS * KW];          // fused W bf16x2 lo plane
__device__ int      g_cnt [N_NODES];            // zero at load; self-restored by scan3
__device__ int      g_scan[N_NODES];
__device__ int      g_bsum[32];
__device__ int      g_cur [N_NODES];
__device__ unsigned g_srcrt[N_EDGES];           // src | rel<<16, sorted by dst
__device__ int      g_dstS [N_EDGES];           // dst, sorted

// ---------------- bf16 helpers ----------------------------------------------
// pack (x0 -> low half, x1 -> high half) with round-to-nearest
__device__ __forceinline__ uint32_t bf16x2_rn(float x0, float x1) {
    uint32_t w;
    asm("cvt.rn.bf16x2.f32 %0, %1, %2;" : "=r"(w) : "f"(x1), "f"(x0));
    return w;
}
// split a pair of floats into bf16x2 hi/lo plane words
__device__ __forceinline__ void bf_split2(float x0, float x1, uint32_t& wh, uint32_t& wl) {
    wh = bf16x2_rn(x0, x1);
    float h0 = __uint_as_float(wh << 16);
    float h1 = __uint_as_float(wh & 0xFFFF0000u);
    wl = bf16x2_rn(x0 - h0, x1 - h1);
}
__device__ __forceinline__ void mma_bf16(float* d, const uint32_t* a, const uint32_t* b) {
    asm volatile("mma.sync.aligned.m16n8k16.row.col.f32.bf16.bf16.f32 "
                 "{%0,%1,%2,%3}, {%4,%5,%6,%7}, {%8,%9}, {%0,%1,%2,%3};"
                 : "+f"(d[0]), "+f"(d[1]), "+f"(d[2]), "+f"(d[3])
                 : "r"(a[0]), "r"(a[1]), "r"(a[2]), "r"(a[3]), "r"(b[0]), "r"(b[1]));
}

// ---------------------------------------------------------------------------
// K1: attention-weight composition.  One block per relation.
// ---------------------------------------------------------------------------
__global__ void __launch_bounds__(320) attn_comp_kernel(const float* __restrict__ aw,
                                                        const float* __restrict__ w_comp,
                                                        const float* __restrict__ fc_w)
{
    __shared__ float afc[128 * NHEADS];
    const int r = blockIdx.x, tid = threadIdx.x;

    if (tid < 128) {
        float acc[NHEADS] = {};
#pragma unroll
        for (int b = 0; b < NBASES; b++) {
            float wc = w_comp[r * NBASES + b];
#pragma unroll
            for (int h = 0; h < NHEADS; h++)
                acc[h] += wc * aw[(b * 128 + tid) * NHEADS + h];
        }
#pragma unroll
        for (int h = 0; h < NHEADS; h++) afc[tid * NHEADS + h] = acc[h];
    }
    __syncthreads();

    for (int o = tid; o < 640; o += 320) {
        int k = o / 10, c2 = o % 10, h = c2 % 5;
        const float* af = afc + (c2 >= 5 ? 64 * NHEADS : 0) + h;
        float sum = 0.f;
#pragma unroll
        for (int f = 0; f < 64; f++) sum += fc_w[k * 64 + f] * af[f * NHEADS];
        g_W2[k * PCOLS + (c2 >= 5 ? 100 : 0) + r * 5 + h] = sum;
    }
}

// ---------------------------------------------------------------------------
// K2: split fused W into packed bf16x2 planes, layout [c][kw] (k-pairs).
// 20480 threads: t -> (c = t>>5, kw = t&31), word packs k = 2kw, 2kw+1.
// ---------------------------------------------------------------------------
__device__ __forceinline__ float wfused(int k, int c,
                                        const float* __restrict__ fc_w,
                                        const float* __restrict__ self_fc_w)
{
    if (c < 64)   return fc_w[k * 64 + c];
    if (c < 384)  return self_fc_w[k * 320 + (c - 64)];
    if (c < TOTC) return g_W2[k * PCOLS + (c - 384)];
    return 0.f;
}

__global__ void __launch_bounds__(256) split_w_kernel(const float* __restrict__ fc_w,
                                                      const float* __restrict__ self_fc_w)
{
    int t = blockIdx.x * 256 + threadIdx.x;
    if (t >= WCOLS * KW) return;
    int c = t >> 5, kw = t & 31;
    float x0 = wfused(2 * kw,     c, fc_w, self_fc_w);
    float x1 = wfused(2 * kw + 1, c, fc_w, self_fc_w);
    uint32_t wh, wl;
    bf_split2(x0, x1, wh, wl);
    g_WbH[t] = wh;
    g_WbL[t] = wl;
}

// ---------------------------------------------------------------------------
// Sort chain: hist -> scan1 -> scan3(+cnt reset) -> scatter
// ---------------------------------------------------------------------------
__global__ void hist_kernel(const int* __restrict__ dst)
{
    int e = blockIdx.x * blockDim.x + threadIdx.x;
    if (e < N_EDGES) atomicAdd(&g_cnt[dst[e]], 1);
}

__global__ void __launch_bounds__(1024) scan1_kernel()
{
    __shared__ int wsum[32];
    const int tid = threadIdx.x, lane = tid & 31, wid = tid >> 5;
    const int idx = blockIdx.x * 1024 + tid;
    int v = (idx < N_NODES) ? g_cnt[idx] : 0;
    int x = v;
#pragma unroll
    for (int d = 1; d < 32; d <<= 1) {
        int y = __shfl_up_sync(0xffffffffu, x, d);
        if (lane >= d) x += y;
    }
    if (lane == 31) wsum[wid] = x;
    __syncthreads();
    if (tid < 32) {
        int w = wsum[tid];
#pragma unroll
        for (int d = 1; d < 32; d <<= 1) {
            int y = __shfl_up_sync(0xffffffffu, w, d);
            if (tid >= d) w += y;
        }
        wsum[tid] = w;
    }
    __syncthreads();
    int incl = x + (wid > 0 ? wsum[wid - 1] : 0);
    if (idx < N_NODES) g_scan[idx] = incl;
    if (tid == 1023)   g_bsum[blockIdx.x] = incl;
}

__global__ void __launch_bounds__(1024) scan3_kernel()
{
    __shared__ int s_pre;
    const int tid = threadIdx.x;
    if (tid < 32) {
        int v = (tid < blockIdx.x) ? g_bsum[tid] : 0;
#pragma unroll
        for (int d = 16; d > 0; d >>= 1) v += __shfl_xor_sync(0xffffffffu, v, d);
        if (tid == 0) s_pre = v;
    }
    __syncthreads();
    int idx = blockIdx.x * 1024 + tid;
    if (idx < N_NODES) {
        int c = g_cnt[idx];
        g_cur[idx] = g_scan[idx] + s_pre - c;
        g_cnt[idx] = 0;                        // self-restore for next replay
    }
}

__global__ void scatter_kernel(const int* __restrict__ dst,
                               const int* __restrict__ src,
                               const int* __restrict__ et)
{
    int e = blockIdx.x * blockDim.x + threadIdx.x;
    if (e < N_EDGES) {
        int d = dst[e];
        int pos = atomicAdd(&g_cur[d], 1);
        g_srcrt[pos] = (unsigned)src[e] | ((unsigned)et[e] << 16);
        g_dstS[pos]  = d;
    }
}

// ---------------------------------------------------------------------------
// proj_mma v6: bf16 2-way split, 3-product MMA (m16n8k16) — half the MMA
// and LDS work of the tf32 version.  Block owns 64 rows, loops 10 chunks.
// smem: AsH/AsL [64][36]w + BsH/BsL [64][36]w = 36.9 KB.  B chunks double-
// buffered through registers (2x uint4 per plane).
// ---------------------------------------------------------------------------
#define PROJ_SMEM (4 * 64 * SSTR * 4)

__global__ void __launch_bounds__(256, 3) proj_mma_kernel(const float* __restrict__ feat,
                                                          float* __restrict__ out)
{
    extern __shared__ uint32_t smem[];
    uint32_t* AsH = smem;                    // [row][kw]
    uint32_t* AsL = AsH + 64 * SSTR;
    uint32_t* BsH = AsL + 64 * SSTR;         // [n][kw]
    uint32_t* BsL = BsH + 64 * SSTR;

    const int tid = threadIdx.x;
    const int m0  = blockIdx.x * 64;

    // B copy indices: thread owns 8 consecutive words (2x uint4) per plane
    const int bn  = tid >> 2;                // n row 0..63
    const int bkw = (tid & 3) * 8;           // kw base 0,8,16,24

    // ---- prefetch chunk 0 B planes into registers
    uint4 hbuf0, hbuf1, lbuf0, lbuf1;
    {
        const uint4* ph = (const uint4*)(g_WbH) + tid * 2;
        const uint4* pl = (const uint4*)(g_WbL) + tid * 2;
        hbuf0 = ph[0]; hbuf1 = ph[1];
        lbuf0 = pl[0]; lbuf1 = pl[1];
    }

    // ---- A tile (64 rows x 64 k): load feat + bf16-split into packed planes
#pragma unroll
    for (int i = 0; i < 4; i++) {
        int v = tid + i * 256;                 // 0..1023 float4 slots
        int row = v >> 4, s = v & 15;
        int kw0 = 2 * s;
        int node = m0 + row;
        float4 a = make_float4(0.f, 0.f, 0.f, 0.f);
        if (node < N_NODES) a = *(const float4*)(feat + node * F + 4 * s);
        uint32_t h0, l0, h1, l1;
        bf_split2(a.x, a.y, h0, l0);
        bf_split2(a.z, a.w, h1, l1);
        *(uint2*)(AsH + row * SSTR + kw0) = make_uint2(h0, h1);
        *(uint2*)(AsL + row * SSTR + kw0) = make_uint2(l0, l1);
    }

    const int wid  = tid >> 5;
    const int lane = tid & 31;
    const int gid  = lane >> 2;       // 0..7
    const int tig  = lane & 3;        // 0..3
    const int wrow = wid & 3;         // row group
    const int wcol = (wid >> 2) * 32; // col half within chunk
    const int rb   = 16 * wrow + gid;
    const int r0   = m0 + rb;

    const uint32_t* aH0 = AsH + rb * SSTR + tig;
    const uint32_t* aH1 = AsH + (rb + 8) * SSTR + tig;
    const uint32_t* aL0 = AsL + rb * SSTR + tig;
    const uint32_t* aL1 = AsL + (rb + 8) * SSTR + tig;

#pragma unroll 1
    for (int c0 = 0; c0 < WCOLS; c0 += 64) {
        __syncthreads();   // prev chunk's MMA readers done (also covers A split @c0=0)
        // ---- store staged B regs -> smem (STS.128 x2 per plane)
        *(uint4*)(BsH + bn * SSTR + bkw)     = hbuf0;
        *(uint4*)(BsH + bn * SSTR + bkw + 4) = hbuf1;
        *(uint4*)(BsL + bn * SSTR + bkw)     = lbuf0;
        *(uint4*)(BsL + bn * SSTR + bkw + 4) = lbuf1;
        __syncthreads();
        // ---- prefetch next chunk's B planes (overlaps MMA below)
        if (c0 + 64 < WCOLS) {
            const uint4* ph = (const uint4*)(g_WbH + (c0 + 64) * KW) + tid * 2;
            const uint4* pl = (const uint4*)(g_WbL + (c0 + 64) * KW) + tid * 2;
            hbuf0 = ph[0]; hbuf1 = ph[1];
            lbuf0 = pl[0]; lbuf1 = pl[1];
        }

        float d[4][4];
#pragma unroll
        for (int j = 0; j < 4; j++)
#pragma unroll
            for (int q = 0; q < 4; q++) d[j][q] = 0.f;

#pragma unroll
        for (int ks = 0; ks < 4; ks++) {
            const int kb = 8 * ks;
            uint32_t ah[4], al[4];
            ah[0] = aH0[kb];     ah[1] = aH1[kb];
            ah[2] = aH0[kb + 4]; ah[3] = aH1[kb + 4];
            al[0] = aL0[kb];     al[1] = aL1[kb];
            al[2] = aL0[kb + 4]; al[3] = aL1[kb + 4];
#pragma unroll
            for (int j = 0; j < 4; j++) {
                const uint32_t* bh = BsH + (wcol + 8 * j + gid) * SSTR + tig;
                const uint32_t* bl = BsL + (wcol + 8 * j + gid) * SSTR + tig;
                uint32_t bhf[2], blf[2];
                bhf[0] = bh[kb]; bhf[1] = bh[kb + 4];
                blf[0] = bl[kb]; blf[1] = bl[kb + 4];
                mma_bf16(d[j], ah, bhf);
                mma_bf16(d[j], al, bhf);
                mma_bf16(d[j], ah, blf);
            }
        }

        // ---- epilogue for this chunk: route to g_z / out / g_P
        const int cb = tig * 2;
#pragma unroll
        for (int j = 0; j < 4; j++) {
            int gc = c0 + wcol + 8 * j + cb;
            if (gc >= TOTC) continue;
#pragma unroll
            for (int half = 0; half < 2; half++) {
                int node = r0 + 8 * half;
                if (node >= N_NODES) continue;
                float x = d[j][2 * half], y = d[j][2 * half + 1];
                if (gc < 64) {
                    *(float2*)(g_z + node * F + gc) = make_float2(x, y);
                } else if (gc < 384) {
                    *(float2*)(out + node * OUTC + (gc - 64)) = make_float2(x, y);
                } else {
#pragma unroll
                    for (int t = 0; t < 2; t++) {
                        int ix = gc - 384 + t;
                        int part = (ix >= 100) ? 8 : 0;
                        int pix  = (ix >= 100) ? ix - 100 : ix;
                        int rr = pix / 5, hh = pix % 5;
                        g_P[node * PSTRIDE + rr * 16 + part + hh] = t ? y : x;
                    }
                }
            }
        }
    }
}

// ---------------------------------------------------------------------------
// gather: edge-parallel aggregation over dst-sorted edges (r12, padded P).
// ---------------------------------------------------------------------------
__global__ void __launch_bounds__(256) gather_kernel(float* __restrict__ out)
{
    __shared__ float stage[8][328];
    const int w = threadIdx.x >> 5, lane = threadIdx.x & 31;
    const int gw = blockIdx.x * 8 + w;
    const int e0 = gw * CHUNK;
    if (e0 >= N_EDGES) return;
    const int e1 = min(e0 + CHUNK, N_EDGES);

    float acc[10];
#pragma unroll
    for (int q = 0; q < 10; q++) acc[q] = 0.f;

    int      d_n = g_dstS[e0];
    unsigned pk  = g_srcrt[e0];
    int s_n = pk & 0xFFFFu, r_n = pk >> 16;
    float2 zs_n = *(const float2*)(g_z + s_n * F + 2 * lane);
    const float* pp = g_P + s_n * PSTRIDE + r_n * 16;
    const float* qq = g_P + d_n * PSTRIDE + r_n * 16 + 8;
    float4 ps4_n = *(const float4*)pp;  float ps1_n = pp[4];
    float4 pd4_n = *(const float4*)qq;  float pd1_n = qq[4];
    int d_cur = d_n;

    for (int i = e0; i < e1; i++) {
        const int    d_c  = d_n;
        const float2 zs   = zs_n;
        const float4 ps4  = ps4_n, pd4 = pd4_n;
        const float  ps1  = ps1_n, pd1 = pd1_n;

        if (i + 1 < e1) {
            d_n = g_dstS[i + 1];
            pk  = g_srcrt[i + 1];
            int s2 = pk & 0xFFFFu, r2 = pk >> 16;
            zs_n = *(const float2*)(g_z + s2 * F + 2 * lane);
            const float* p2 = g_P + s2 * PSTRIDE + r2 * 16;
            const float* p3 = g_P + d_n * PSTRIDE + r2 * 16 + 8;
            ps4_n = *(const float4*)p2;  ps1_n = p2[4];
            pd4_n = *(const float4*)p3;  pd1_n = p3[4];
        }

        if (d_c != d_cur) {   // warp-uniform branch
#pragma unroll
            for (int h = 0; h < NHEADS; h++)
                *(float2*)&stage[w][h * F + 2 * lane] = make_float2(acc[2 * h], acc[2 * h + 1]);
            __syncwarp();
            float* ob = out + (long)d_cur * OUTC;
#pragma unroll
            for (int t = 0; t < 3; t++) {
                int cc = lane + 32 * t;
                if (cc < 80) {
                    float4 v = *(const float4*)&stage[w][cc * 4];
                    asm volatile("red.global.add.v4.f32 [%0], {%1, %2, %3, %4};"
                                 :: "l"(ob + 4 * cc), "f"(v.x), "f"(v.y), "f"(v.z), "f"(v.w)
                                 : "memory");
                }
            }
            __syncwarp();
#pragma unroll
            for (int q = 0; q < 10; q++) acc[q] = 0.f;
            d_cur = d_c;
        }

        float a0 = ps4.x + pd4.x;  a0 = a0 > 0.f ? a0 : 0.01f * a0;
        float a1 = ps4.y + pd4.y;  a1 = a1 > 0.f ? a1 : 0.01f * a1;
        float a2 = ps4.z + pd4.z;  a2 = a2 > 0.f ? a2 : 0.01f * a2;
        float a3 = ps4.w + pd4.w;  a3 = a3 > 0.f ? a3 : 0.01f * a3;
        float a4 = ps1   + pd1;    a4 = a4 > 0.f ? a4 : 0.01f * a4;
        acc[0] += a0 * zs.x;  acc[1] += a0 * zs.y;
        acc[2] += a1 * zs.x;  acc[3] += a1 * zs.y;
        acc[4] += a2 * zs.x;  acc[5] += a2 * zs.y;
        acc[6] += a3 * zs.x;  acc[7] += a3 * zs.y;
        acc[8] += a4 * zs.x;  acc[9] += a4 * zs.y;
    }

    // final flush
#pragma unroll
    for (int h = 0; h < NHEADS; h++)
        *(float2*)&stage[w][h * F + 2 * lane] = make_float2(acc[2 * h], acc[2 * h + 1]);
    __syncwarp();
    float* ob = out + (long)d_cur * OUTC;
#pragma unroll
    for (int t = 0; t < 3; t++) {
        int cc = lane + 32 * t;
        if (cc < 80) {
            float4 v = *(const float4*)&stage[w][cc * 4];
            asm volatile("red.global.add.v4.f32 [%0], {%1, %2, %3, %4};"
                         :: "l"(ob + 4 * cc), "f"(v.x), "f"(v.y), "f"(v.z), "f"(v.w)
                         : "memory");
        }
    }
}

// ---------------------------------------------------------------------------
extern "C" void kernel_launch(void* const* d_in, const int* in_sizes, int n_in,
                              void* d_out, int out_size)
{
    const float* feat      = (const float*)d_in[0];
    const int*   src       = (const int*)  d_in[1];
    const int*   dst       = (const int*)  d_in[2];
    const int*   etype     = (const int*)  d_in[3];
    const float* fc_w      = (const float*)d_in[4];
    const float* self_fc_w = (const float*)d_in[5];
    const float* aw        = (const float*)d_in[6];
    const float* w_comp    = (const float*)d_in[7];
    float* out = (float*)d_out;

    const int NB = (N_NODES + 1023) / 1024;   // 25

    static cudaStream_t s_side = nullptr;
    static cudaEvent_t  ev_fork = nullptr, ev_sort = nullptr;
    if (s_side == nullptr) {
        cudaStreamCreateWithFlags(&s_side, cudaStreamNonBlocking);
        cudaEventCreateWithFlags(&ev_fork, cudaEventDisableTiming);
        cudaEventCreateWithFlags(&ev_sort, cudaEventDisableTiming);
        cudaFuncSetAttribute(proj_mma_kernel,
                             cudaFuncAttributeMaxDynamicSharedMemorySize, PROJ_SMEM);
    }

    // ---- fork: sort chain on side stream (independent of weights/proj)
    cudaEventRecord(ev_fork, 0);
    cudaStreamWaitEvent(s_side, ev_fork, 0);
    hist_kernel<<<(N_EDGES + 255) / 256, 256, 0, s_side>>>(dst);
    scan1_kernel<<<NB, 1024, 0, s_side>>>();
    scan3_kernel<<<NB, 1024, 0, s_side>>>();
    scatter_kernel<<<(N_EDGES + 255) / 256, 256, 0, s_side>>>(dst, src, etype);
    cudaEventRecord(ev_sort, s_side);

    // ---- main stream: weights -> projection GEMM
    attn_comp_kernel<<<NRELS, 320>>>(aw, w_comp, fc_w);
    split_w_kernel<<<(WCOLS * KW + 255) / 256, 256>>>(fc_w, self_fc_w);
    proj_mma_kernel<<<(N_NODES + 63) / 64, 256, PROJ_SMEM>>>(feat, out);

    // ---- join, then gather
    cudaStreamWaitEvent(0, ev_sort, 0);
    gather_kernel<<<(N_EDGES / CHUNK + 7) / 8, 256>>>(out);
}

// round 14
// speedup vs baseline: 1.7188x; 1.0802x over previous
#include <cuda_runtime.h>
#include <cstdint>

#define N_NODES 25000
#define N_EDGES 320000
#define F       64
#define NHEADS  5
#define NRELS   20
#define NBASES  10
#define OUTC    320
#define PCOLS   200          // GEMM P-columns (compact): 100 s + 100 d
#define PSTRIDE 320          // padded per-node P row: 20 rels * 16
#define TOTC    584          // 64 z + 320 self_z + 200 P
#define WCOLS   640          // padded fused-W width
#define CHUNK   32
#define KW      32           // k-words per column (64 k / 2 per word)
#define SSTR    36           // smem row stride (words), conflict-free

// ---------------- static device scratch ------------------------------------
__device__ float    g_z [N_NODES * F];          // 6.4 MB
__device__ float    g_W2[64 * PCOLS];
__device__ float    g_P [N_NODES * PSTRIDE];    // 32 MB padded
__device__ uint32_t g_WbH[WCOLS * KW];          // fused W bf16x2 hi plane, [c][kw]
__device__ uint32_t g_WbL[WCOLS * KW];          // fused W bf16x2 lo plane
__device__ int      g_cnt [N_NODES];            // zero at load; self-restored by scan3
__device__ int      g_scan[N_NODES];
__device__ int      g_bsum[32];
__device__ int      g_cur [N_NODES];
__device__ unsigned g_srcrt[N_EDGES];           // src | rel<<16, sorted by dst
__device__ int      g_dstS [N_EDGES];           // dst, sorted

// ---------------- bf16 helpers ----------------------------------------------
__device__ __forceinline__ uint32_t bf16x2_rn(float x0, float x1) {
    uint32_t w;
    asm("cvt.rn.bf16x2.f32 %0, %1, %2;" : "=r"(w) : "f"(x1), "f"(x0));
    return w;
}
__device__ __forceinline__ void bf_split2(float x0, float x1, uint32_t& wh, uint32_t& wl) {
    wh = bf16x2_rn(x0, x1);
    float h0 = __uint_as_float(wh << 16);
    float h1 = __uint_as_float(wh & 0xFFFF0000u);
    wl = bf16x2_rn(x0 - h0, x1 - h1);
}
__device__ __forceinline__ void mma_bf16(float* d, const uint32_t* a, const uint32_t* b) {
    asm volatile("mma.sync.aligned.m16n8k16.row.col.f32.bf16.bf16.f32 "
                 "{%0,%1,%2,%3}, {%4,%5,%6,%7}, {%8,%9}, {%0,%1,%2,%3};"
                 : "+f"(d[0]), "+f"(d[1]), "+f"(d[2]), "+f"(d[3])
                 : "r"(a[0]), "r"(a[1]), "r"(a[2]), "r"(a[3]), "r"(b[0]), "r"(b[1]));
}

// ---------------------------------------------------------------------------
// K1: attention-weight composition.  One block per relation.
// ---------------------------------------------------------------------------
__global__ void __launch_bounds__(320) attn_comp_kernel(const float* __restrict__ aw,
                                                        const float* __restrict__ w_comp,
                                                        const float* __restrict__ fc_w)
{
    __shared__ float afc[128 * NHEADS];
    const int r = blockIdx.x, tid = threadIdx.x;

    if (tid < 128) {
        float acc[NHEADS] = {};
#pragma unroll
        for (int b = 0; b < NBASES; b++) {
            float wc = w_comp[r * NBASES + b];
#pragma unroll
            for (int h = 0; h < NHEADS; h++)
                acc[h] += wc * aw[(b * 128 + tid) * NHEADS + h];
        }
#pragma unroll
        for (int h = 0; h < NHEADS; h++) afc[tid * NHEADS + h] = acc[h];
    }
    __syncthreads();

    for (int o = tid; o < 640; o += 320) {
        int k = o / 10, c2 = o % 10, h = c2 % 5;
        const float* af = afc + (c2 >= 5 ? 64 * NHEADS : 0) + h;
        float sum = 0.f;
#pragma unroll
        for (int f = 0; f < 64; f++) sum += fc_w[k * 64 + f] * af[f * NHEADS];
        g_W2[k * PCOLS + (c2 >= 5 ? 100 : 0) + r * 5 + h] = sum;
    }
}

// ---------------------------------------------------------------------------
// K2: split fused W into packed bf16x2 planes, layout [c][kw] (k-pairs).
// ---------------------------------------------------------------------------
__device__ __forceinline__ float wfused(int k, int c,
                                        const float* __restrict__ fc_w,
                                        const float* __restrict__ self_fc_w)
{
    if (c < 64)   return fc_w[k * 64 + c];
    if (c < 384)  return self_fc_w[k * 320 + (c - 64)];
    if (c < TOTC) return g_W2[k * PCOLS + (c - 384)];
    return 0.f;
}

__global__ void __launch_bounds__(256) split_w_kernel(const float* __restrict__ fc_w,
                                                      const float* __restrict__ self_fc_w)
{
    int t = blockIdx.x * 256 + threadIdx.x;
    if (t >= WCOLS * KW) return;
    int c = t >> 5, kw = t & 31;
    float x0 = wfused(2 * kw,     c, fc_w, self_fc_w);
    float x1 = wfused(2 * kw + 1, c, fc_w, self_fc_w);
    uint32_t wh, wl;
    bf_split2(x0, x1, wh, wl);
    g_WbH[t] = wh;
    g_WbL[t] = wl;
}

// ---------------------------------------------------------------------------
// Sort chain: hist -> scan1 -> scan3(+cnt reset) -> scatter
// ---------------------------------------------------------------------------
__global__ void hist_kernel(const int* __restrict__ dst)
{
    int e = blockIdx.x * blockDim.x + threadIdx.x;
    if (e < N_EDGES) atomicAdd(&g_cnt[dst[e]], 1);
}

__global__ void __launch_bounds__(1024) scan1_kernel()
{
    __shared__ int wsum[32];
    const int tid = threadIdx.x, lane = tid & 31, wid = tid >> 5;
    const int idx = blockIdx.x * 1024 + tid;
    int v = (idx < N_NODES) ? g_cnt[idx] : 0;
    int x = v;
#pragma unroll
    for (int d = 1; d < 32; d <<= 1) {
        int y = __shfl_up_sync(0xffffffffu, x, d);
        if (lane >= d) x += y;
    }
    if (lane == 31) wsum[wid] = x;
    __syncthreads();
    if (tid < 32) {
        int w = wsum[tid];
#pragma unroll
        for (int d = 1; d < 32; d <<= 1) {
            int y = __shfl_up_sync(0xffffffffu, w, d);
            if (tid >= d) w += y;
        }
        wsum[tid] = w;
    }
    __syncthreads();
    int incl = x + (wid > 0 ? wsum[wid - 1] : 0);
    if (idx < N_NODES) g_scan[idx] = incl;
    if (tid == 1023)   g_bsum[blockIdx.x] = incl;
}

__global__ void __launch_bounds__(1024) scan3_kernel()
{
    __shared__ int s_pre;
    const int tid = threadIdx.x;
    if (tid < 32) {
        int v = (tid < blockIdx.x) ? g_bsum[tid] : 0;
#pragma unroll
        for (int d = 16; d > 0; d >>= 1) v += __shfl_xor_sync(0xffffffffu, v, d);
        if (tid == 0) s_pre = v;
    }
    __syncthreads();
    int idx = blockIdx.x * 1024 + tid;
    if (idx < N_NODES) {
        int c = g_cnt[idx];
        g_cur[idx] = g_scan[idx] + s_pre - c;
        g_cnt[idx] = 0;                        // self-restore for next replay
    }
}

__global__ void scatter_kernel(const int* __restrict__ dst,
                               const int* __restrict__ src,
                               const int* __restrict__ et)
{
    int e = blockIdx.x * blockDim.x + threadIdx.x;
    if (e < N_EDGES) {
        int d = dst[e];
        int pos = atomicAdd(&g_cur[d], 1);
        g_srcrt[pos] = (unsigned)src[e] | ((unsigned)et[e] << 16);
        g_dstS[pos]  = d;
    }
}

// ---------------------------------------------------------------------------
// proj_mma v6: bf16 2-way split, 3-product MMA (m16n8k16).  Unchanged (r13).
// ---------------------------------------------------------------------------
#define PROJ_SMEM (4 * 64 * SSTR * 4)

__global__ void __launch_bounds__(256, 3) proj_mma_kernel(const float* __restrict__ feat,
                                                          float* __restrict__ out)
{
    extern __shared__ uint32_t smem[];
    uint32_t* AsH = smem;                    // [row][kw]
    uint32_t* AsL = AsH + 64 * SSTR;
    uint32_t* BsH = AsL + 64 * SSTR;         // [n][kw]
    uint32_t* BsL = BsH + 64 * SSTR;

    const int tid = threadIdx.x;
    const int m0  = blockIdx.x * 64;

    const int bn  = tid >> 2;                // n row 0..63
    const int bkw = (tid & 3) * 8;           // kw base 0,8,16,24

    // ---- prefetch chunk 0 B planes into registers
    uint4 hbuf0, hbuf1, lbuf0, lbuf1;
    {
        const uint4* ph = (const uint4*)(g_WbH) + tid * 2;
        const uint4* pl = (const uint4*)(g_WbL) + tid * 2;
        hbuf0 = ph[0]; hbuf1 = ph[1];
        lbuf0 = pl[0]; lbuf1 = pl[1];
    }

    // ---- A tile (64 rows x 64 k): load feat + bf16-split into packed planes
#pragma unroll
    for (int i = 0; i < 4; i++) {
        int v = tid + i * 256;                 // 0..1023 float4 slots
        int row = v >> 4, s = v & 15;
        int kw0 = 2 * s;
        int node = m0 + row;
        float4 a = make_float4(0.f, 0.f, 0.f, 0.f);
        if (node < N_NODES) a = *(const float4*)(feat + node * F + 4 * s);
        uint32_t h0, l0, h1, l1;
        bf_split2(a.x, a.y, h0, l0);
        bf_split2(a.z, a.w, h1, l1);
        *(uint2*)(AsH + row * SSTR + kw0) = make_uint2(h0, h1);
        *(uint2*)(AsL + row * SSTR + kw0) = make_uint2(l0, l1);
    }

    const int wid  = tid >> 5;
    const int lane = tid & 31;
    const int gid  = lane >> 2;       // 0..7
    const int tig  = lane & 3;        // 0..3
    const int wrow = wid & 3;         // row group
    const int wcol = (wid >> 2) * 32; // col half within chunk
    const int rb   = 16 * wrow + gid;
    const int r0   = m0 + rb;

    const uint32_t* aH0 = AsH + rb * SSTR + tig;
    const uint32_t* aH1 = AsH + (rb + 8) * SSTR + tig;
    const uint32_t* aL0 = AsL + rb * SSTR + tig;
    const uint32_t* aL1 = AsL + (rb + 8) * SSTR + tig;

#pragma unroll 1
    for (int c0 = 0; c0 < WCOLS; c0 += 64) {
        __syncthreads();   // prev chunk's MMA readers done (also covers A split @c0=0)
        *(uint4*)(BsH + bn * SSTR + bkw)     = hbuf0;
        *(uint4*)(BsH + bn * SSTR + bkw + 4) = hbuf1;
        *(uint4*)(BsL + bn * SSTR + bkw)     = lbuf0;
        *(uint4*)(BsL + bn * SSTR + bkw + 4) = lbuf1;
        __syncthreads();
        if (c0 + 64 < WCOLS) {
            const uint4* ph = (const uint4*)(g_WbH + (c0 + 64) * KW) + tid * 2;
            const uint4* pl = (const uint4*)(g_WbL + (c0 + 64) * KW) + tid * 2;
            hbuf0 = ph[0]; hbuf1 = ph[1];
            lbuf0 = pl[0]; lbuf1 = pl[1];
        }

        float d[4][4];
#pragma unroll
        for (int j = 0; j < 4; j++)
#pragma unroll
            for (int q = 0; q < 4; q++) d[j][q] = 0.f;

#pragma unroll
        for (int ks = 0; ks < 4; ks++) {
            const int kb = 8 * ks;
            uint32_t ah[4], al[4];
            ah[0] = aH0[kb];     ah[1] = aH1[kb];
            ah[2] = aH0[kb + 4]; ah[3] = aH1[kb + 4];
            al[0] = aL0[kb];     al[1] = aL1[kb];
            al[2] = aL0[kb + 4]; al[3] = aL1[kb + 4];
#pragma unroll
            for (int j = 0; j < 4; j++) {
                const uint32_t* bh = BsH + (wcol + 8 * j + gid) * SSTR + tig;
                const uint32_t* bl = BsL + (wcol + 8 * j + gid) * SSTR + tig;
                uint32_t bhf[2], blf[2];
                bhf[0] = bh[kb]; bhf[1] = bh[kb + 4];
                blf[0] = bl[kb]; blf[1] = bl[kb + 4];
                mma_bf16(d[j], ah, bhf);
                mma_bf16(d[j], al, bhf);
                mma_bf16(d[j], ah, blf);
            }
        }

        const int cb = tig * 2;
#pragma unroll
        for (int j = 0; j < 4; j++) {
            int gc = c0 + wcol + 8 * j + cb;
            if (gc >= TOTC) continue;
#pragma unroll
            for (int half = 0; half < 2; half++) {
                int node = r0 + 8 * half;
                if (node >= N_NODES) continue;
                float x = d[j][2 * half], y = d[j][2 * half + 1];
                if (gc < 64) {
                    *(float2*)(g_z + node * F + gc) = make_float2(x, y);
                } else if (gc < 384) {
                    *(float2*)(out + node * OUTC + (gc - 64)) = make_float2(x, y);
                } else {
#pragma unroll
                    for (int t = 0; t < 2; t++) {
                        int ix = gc - 384 + t;
                        int part = (ix >= 100) ? 8 : 0;
                        int pix  = (ix >= 100) ? ix - 100 : ix;
                        int rr = pix / 5, hh = pix % 5;
                        g_P[node * PSTRIDE + rr * 16 + part + hh] = t ? y : x;
                    }
                }
            }
        }
    }
}

// ---------------------------------------------------------------------------
// gather v2: lane-distributed index prefetch (shfl) + direct red.v2 flushes.
// Warp owns CHUNK=32 sorted edges; lane i pre-loads edge e0+i's indices.
// ---------------------------------------------------------------------------
__global__ void __launch_bounds__(256) gather_kernel(float* __restrict__ out)
{
    const int w = threadIdx.x >> 5, lane = threadIdx.x & 31;
    const int gw = blockIdx.x * 8 + w;
    const int e0 = gw * CHUNK;
    if (e0 >= N_EDGES) return;

    // lane-parallel index load for the whole chunk (coalesced)
    const unsigned pk_all = g_srcrt[e0 + lane];
    const int      dd_all = g_dstS [e0 + lane];

    float acc[10];
#pragma unroll
    for (int q = 0; q < 10; q++) acc[q] = 0.f;

    // prefetch edge 0 data
    unsigned pk = __shfl_sync(0xffffffffu, pk_all, 0);
    int d_n = __shfl_sync(0xffffffffu, dd_all, 0);
    int s0 = pk & 0xFFFFu, rr0 = pk >> 16;
    float2 zs_n = *(const float2*)(g_z + s0 * F + 2 * lane);
    const float* pp = g_P + s0 * PSTRIDE + rr0 * 16;
    const float* qq = g_P + d_n * PSTRIDE + rr0 * 16 + 8;
    float4 ps4_n = *(const float4*)pp;  float ps1_n = pp[4];
    float4 pd4_n = *(const float4*)qq;  float pd1_n = qq[4];
    int d_cur = d_n;

#pragma unroll 4
    for (int i = 0; i < CHUNK; i++) {
        const int    d_c  = d_n;
        const float2 zs   = zs_n;
        const float4 ps4  = ps4_n, pd4 = pd4_n;
        const float  ps1  = ps1_n, pd1 = pd1_n;

        if (i + 1 < CHUNK) {
            unsigned pk2 = __shfl_sync(0xffffffffu, pk_all, i + 1);
            d_n = __shfl_sync(0xffffffffu, dd_all, i + 1);
            int s2 = pk2 & 0xFFFFu, r2 = pk2 >> 16;
            zs_n = *(const float2*)(g_z + s2 * F + 2 * lane);
            const float* p2 = g_P + s2 * PSTRIDE + r2 * 16;
            const float* p3 = g_P + d_n * PSTRIDE + r2 * 16 + 8;
            ps4_n = *(const float4*)p2;  ps1_n = p2[4];
            pd4_n = *(const float4*)p3;  pd1_n = p3[4];
        }

        if (d_c != d_cur) {   // warp-uniform branch: flush accumulator
            float* ob = out + (long)d_cur * OUTC + 2 * lane;
#pragma unroll
            for (int h = 0; h < NHEADS; h++)
                asm volatile("red.global.add.v2.f32 [%0], {%1, %2};"
                             :: "l"(ob + h * F), "f"(acc[2 * h]), "f"(acc[2 * h + 1])
                             : "memory");
#pragma unroll
            for (int q = 0; q < 10; q++) acc[q] = 0.f;
            d_cur = d_c;
        }

        float a0 = ps4.x + pd4.x;  a0 = a0 > 0.f ? a0 : 0.01f * a0;
        float a1 = ps4.y + pd4.y;  a1 = a1 > 0.f ? a1 : 0.01f * a1;
        float a2 = ps4.z + pd4.z;  a2 = a2 > 0.f ? a2 : 0.01f * a2;
        float a3 = ps4.w + pd4.w;  a3 = a3 > 0.f ? a3 : 0.01f * a3;
        float a4 = ps1   + pd1;    a4 = a4 > 0.f ? a4 : 0.01f * a4;
        acc[0] += a0 * zs.x;  acc[1] += a0 * zs.y;
        acc[2] += a1 * zs.x;  acc[3] += a1 * zs.y;
        acc[4] += a2 * zs.x;  acc[5] += a2 * zs.y;
        acc[6] += a3 * zs.x;  acc[7] += a3 * zs.y;
        acc[8] += a4 * zs.x;  acc[9] += a4 * zs.y;
    }

    // final flush
    float* ob = out + (long)d_cur * OUTC + 2 * lane;
#pragma unroll
    for (int h = 0; h < NHEADS; h++)
        asm volatile("red.global.add.v2.f32 [%0], {%1, %2};"
                     :: "l"(ob + h * F), "f"(acc[2 * h]), "f"(acc[2 * h + 1])
                     : "memory");
}

// ---------------------------------------------------------------------------
extern "C" void kernel_launch(void* const* d_in, const int* in_sizes, int n_in,
                              void* d_out, int out_size)
{
    const float* feat      = (const float*)d_in[0];
    const int*   src       = (const int*)  d_in[1];
    const int*   dst       = (const int*)  d_in[2];
    const int*   etype     = (const int*)  d_in[3];
    const float* fc_w      = (const float*)d_in[4];
    const float* self_fc_w = (const float*)d_in[5];
    const float* aw        = (const float*)d_in[6];
    const float* w_comp    = (const float*)d_in[7];
    float* out = (float*)d_out;

    const int NB = (N_NODES + 1023) / 1024;   // 25

    static cudaStream_t s_side = nullptr;
    static cudaEvent_t  ev_fork = nullptr, ev_sort = nullptr;
    if (s_side == nullptr) {
        cudaStreamCreateWithFlags(&s_side, cudaStreamNonBlocking);
        cudaEventCreateWithFlags(&ev_fork, cudaEventDisableTiming);
        cudaEventCreateWithFlags(&ev_sort, cudaEventDisableTiming);
        cudaFuncSetAttribute(proj_mma_kernel,
                             cudaFuncAttributeMaxDynamicSharedMemorySize, PROJ_SMEM);
    }

    // ---- fork: sort chain on side stream (independent of weights/proj)
    cudaEventRecord(ev_fork, 0);
    cudaStreamWaitEvent(s_side, ev_fork, 0);
    hist_kernel<<<(N_EDGES + 255) / 256, 256, 0, s_side>>>(dst);
    scan1_kernel<<<NB, 1024, 0, s_side>>>();
    scan3_kernel<<<NB, 1024, 0, s_side>>>();
    scatter_kernel<<<(N_EDGES + 255) / 256, 256, 0, s_side>>>(dst, src, etype);
    cudaEventRecord(ev_sort, s_side);

    // ---- main stream: weights -> projection GEMM
    attn_comp_kernel<<<NRELS, 320>>>(aw, w_comp, fc_w);
    split_w_kernel<<<(WCOLS * KW + 255) / 256, 256>>>(fc_w, self_fc_w);
    proj_mma_kernel<<<(N_NODES + 63) / 64, 256, PROJ_SMEM>>>(feat, out);

    // ---- join, then gather
    cudaStreamWaitEvent(0, ev_sort, 0);
    gather_kernel<<<(N_EDGES / CHUNK + 7) / 8, 256>>>(out);
}

// round 15
// speedup vs baseline: 1.7604x; 1.0242x over previous
#include <cuda_runtime.h>
#include <cstdint>

#define N_NODES 25000
#define N_EDGES 320000
#define F       64
#define NHEADS  5
#define NRELS   20
#define NBASES  10
#define OUTC    320
#define PSTRIDE 320          // padded per-node P row: 20 rels * 16
#define TOTC    584          // 64 z + 320 self_z + 200 P
#define WCOLS   640          // padded fused-W width
#define CHUNK   32
#define KW      32           // k-words per column (64 k / 2 per word)
#define SSTR    36           // smem row stride (words), conflict-free

// ---------------- static device scratch ------------------------------------
__device__ float    g_z [N_NODES * F];          // 6.4 MB
__device__ float    g_P [N_NODES * PSTRIDE];    // 32 MB padded
__device__ uint32_t g_WbH[WCOLS * KW];          // fused W bf16x2 hi plane, [c][kw]
__device__ uint32_t g_WbL[WCOLS * KW];          // fused W bf16x2 lo plane
__device__ int      g_cnt [N_NODES];            // zero at load; self-restored by scan3
__device__ int      g_scan[N_NODES];
__device__ int      g_bsum[32];
__device__ int      g_cur [N_NODES];
__device__ unsigned g_srcrt[N_EDGES];           // src | rel<<16, sorted by dst
__device__ int      g_dstS [N_EDGES];           // dst, sorted

// ---------------- bf16 helpers ----------------------------------------------
__device__ __forceinline__ uint32_t bf16x2_rn(float x0, float x1) {
    uint32_t w;
    asm("cvt.rn.bf16x2.f32 %0, %1, %2;" : "=r"(w) : "f"(x1), "f"(x0));
    return w;
}
__device__ __forceinline__ void bf_split2(float x0, float x1, uint32_t& wh, uint32_t& wl) {
    wh = bf16x2_rn(x0, x1);
    float h0 = __uint_as_float(wh << 16);
    float h1 = __uint_as_float(wh & 0xFFFF0000u);
    wl = bf16x2_rn(x0 - h0, x1 - h1);
}
__device__ __forceinline__ void mma_bf16(float* d, const uint32_t* a, const uint32_t* b) {
    asm volatile("mma.sync.aligned.m16n8k16.row.col.f32.bf16.bf16.f32 "
                 "{%0,%1,%2,%3}, {%4,%5,%6,%7}, {%8,%9}, {%0,%1,%2,%3};"
                 : "+f"(d[0]), "+f"(d[1]), "+f"(d[2]), "+f"(d[3])
                 : "r"(a[0]), "r"(a[1]), "r"(a[2]), "r"(a[3]), "r"(b[0]), "r"(b[1]));
}

// ---------------------------------------------------------------------------
// K1: attention-weight composition + DIRECT bf16x2 pack of W cols 384..583.
// One block per relation, 320 thr: tid -> (kw = tid/10, c2 = tid%10).
// ---------------------------------------------------------------------------
__global__ void __launch_bounds__(320) attn_comp_kernel(const float* __restrict__ aw,
                                                        const float* __restrict__ w_comp,
                                                        const float* __restrict__ fc_w)
{
    __shared__ float afc[128 * NHEADS];
    const int r = blockIdx.x, tid = threadIdx.x;

    if (tid < 128) {
        float acc[NHEADS] = {};
#pragma unroll
        for (int b = 0; b < NBASES; b++) {
            float wc = w_comp[r * NBASES + b];
#pragma unroll
            for (int h = 0; h < NHEADS; h++)
                acc[h] += wc * aw[(b * 128 + tid) * NHEADS + h];
        }
#pragma unroll
        for (int h = 0; h < NHEADS; h++) afc[tid * NHEADS + h] = acc[h];
    }
    __syncthreads();

    const int kw = tid / 10;            // 0..31
    const int c2 = tid % 10;
    const int h  = c2 % 5;
    const float* af = afc + (c2 >= 5 ? 64 * NHEADS : 0) + h;
    const float* w0 = fc_w + (2 * kw) * 64;
    const float* w1 = fc_w + (2 * kw + 1) * 64;
    float s0 = 0.f, s1 = 0.f;
#pragma unroll
    for (int f = 0; f < 64; f++) {
        float a = af[f * NHEADS];
        s0 += w0[f] * a;
        s1 += w1[f] * a;
    }
    int col = 384 + (c2 >= 5 ? 100 : 0) + r * 5 + h;
    uint32_t wh, wl;
    bf_split2(s0, s1, wh, wl);
    g_WbH[col * KW + kw] = wh;
    g_WbL[col * KW + kw] = wl;
}

// ---------------------------------------------------------------------------
// K2: split W cols 0..383 (+ zero-pad >= 584) into packed bf16x2 planes.
// Cols 384..583 are written by attn_comp_kernel.
// ---------------------------------------------------------------------------
__global__ void __launch_bounds__(256) split_w_kernel(const float* __restrict__ fc_w,
                                                      const float* __restrict__ self_fc_w)
{
    int t = blockIdx.x * 256 + threadIdx.x;
    if (t >= WCOLS * KW) return;
    int c = t >> 5, kw = t & 31;
    if (c >= 384 && c < TOTC) return;    // attn kernel owns these
    float x0 = 0.f, x1 = 0.f;
    if (c < 64) {
        x0 = fc_w[(2 * kw) * 64 + c];
        x1 = fc_w[(2 * kw + 1) * 64 + c];
    } else if (c < 384) {
        x0 = self_fc_w[(2 * kw) * 320 + (c - 64)];
        x1 = self_fc_w[(2 * kw + 1) * 320 + (c - 64)];
    }
    uint32_t wh, wl;
    bf_split2(x0, x1, wh, wl);
    g_WbH[t] = wh;
    g_WbL[t] = wl;
}

// ---------------------------------------------------------------------------
// Sort chain: hist -> scan1 -> scan3(+cnt reset) -> scatter
// ---------------------------------------------------------------------------
__global__ void hist_kernel(const int* __restrict__ dst)
{
    int e = blockIdx.x * blockDim.x + threadIdx.x;
    if (e < N_EDGES) atomicAdd(&g_cnt[dst[e]], 1);
}

__global__ void __launch_bounds__(1024) scan1_kernel()
{
    __shared__ int wsum[32];
    const int tid = threadIdx.x, lane = tid & 31, wid = tid >> 5;
    const int idx = blockIdx.x * 1024 + tid;
    int v = (idx < N_NODES) ? g_cnt[idx] : 0;
    int x = v;
#pragma unroll
    for (int d = 1; d < 32; d <<= 1) {
        int y = __shfl_up_sync(0xffffffffu, x, d);
        if (lane >= d) x += y;
    }
    if (lane == 31) wsum[wid] = x;
    __syncthreads();
    if (tid < 32) {
        int w = wsum[tid];
#pragma unroll
        for (int d = 1; d < 32; d <<= 1) {
            int y = __shfl_up_sync(0xffffffffu, w, d);
            if (tid >= d) w += y;
        }
        wsum[tid] = w;
    }
    __syncthreads();
    int incl = x + (wid > 0 ? wsum[wid - 1] : 0);
    if (idx < N_NODES) g_scan[idx] = incl;
    if (tid == 1023)   g_bsum[blockIdx.x] = incl;
}

__global__ void __launch_bounds__(1024) scan3_kernel()
{
    __shared__ int s_pre;
    const int tid = threadIdx.x;
    if (tid < 32) {
        int v = (tid < blockIdx.x) ? g_bsum[tid] : 0;
#pragma unroll
        for (int d = 16; d > 0; d >>= 1) v += __shfl_xor_sync(0xffffffffu, v, d);
        if (tid == 0) s_pre = v;
    }
    __syncthreads();
    int idx = blockIdx.x * 1024 + tid;
    if (idx < N_NODES) {
        int c = g_cnt[idx];
        g_cur[idx] = g_scan[idx] + s_pre - c;
        g_cnt[idx] = 0;                        // self-restore for next replay
    }
}

__global__ void scatter_kernel(const int* __restrict__ dst,
                               const int* __restrict__ src,
                               const int* __restrict__ et)
{
    int e = blockIdx.x * blockDim.x + threadIdx.x;
    if (e < N_EDGES) {
        int d = dst[e];
        int pos = atomicAdd(&g_cur[d], 1);
        g_srcrt[pos] = (unsigned)src[e] | ((unsigned)et[e] << 16);
        g_dstS[pos]  = d;
    }
}

// ---------------------------------------------------------------------------
// proj_mma v7: bf16 3-product MMA with
//  - A fragments hoisted to registers (chunk-invariant)
//  - double-buffered B smem, ONE sync per chunk (A region reused as buf0)
// smem: 2 buffers x (H+L planes of [64][36]w) = 36.9 KB -> 3 blocks/SM.
// ---------------------------------------------------------------------------
#define BUFW (2 * 64 * SSTR)                 // words per buffer (H+L)
#define PROJ_SMEM (2 * BUFW * 4)

__global__ void __launch_bounds__(256, 3) proj_mma_kernel(const float* __restrict__ feat,
                                                          float* __restrict__ out)
{
    extern __shared__ uint32_t smem[];
    uint32_t* const buf0 = smem;
    uint32_t* const buf1 = smem + BUFW;

    const int tid = threadIdx.x;
    const int m0  = blockIdx.x * 64;
    const int bn  = tid >> 2;                // B-copy n row 0..63
    const int bkw = (tid & 3) * 8;           // B-copy kw base

    // ---- stage chunk 0 B planes into registers
    uint4 h0, h1, l0, l1;
    {
        const uint4* ph = (const uint4*)(g_WbH) + tid * 2;
        const uint4* pl = (const uint4*)(g_WbL) + tid * 2;
        h0 = ph[0]; h1 = ph[1]; l0 = pl[0]; l1 = pl[1];
    }

    // ---- A tile split into buf0 (temporarily A planes)
    uint32_t* AsH = buf0;
    uint32_t* AsL = buf0 + 64 * SSTR;
#pragma unroll
    for (int i = 0; i < 4; i++) {
        int v = tid + i * 256;
        int row = v >> 4, s = v & 15;
        int node = m0 + row;
        float4 a = make_float4(0.f, 0.f, 0.f, 0.f);
        if (node < N_NODES) a = *(const float4*)(feat + node * F + 4 * s);
        uint32_t ah0, al0, ah1, al1;
        bf_split2(a.x, a.y, ah0, al0);
        bf_split2(a.z, a.w, ah1, al1);
        *(uint2*)(AsH + row * SSTR + 2 * s) = make_uint2(ah0, ah1);
        *(uint2*)(AsL + row * SSTR + 2 * s) = make_uint2(al0, al1);
    }
    __syncthreads();

    const int wid  = tid >> 5;
    const int lane = tid & 31;
    const int gid  = lane >> 2;
    const int tig  = lane & 3;
    const int wrow = wid & 3;
    const int wcol = (wid >> 2) * 32;
    const int rb   = 16 * wrow + gid;
    const int r0   = m0 + rb;

    // ---- hoist A fragments (chunk-invariant) into registers
    uint32_t ahr[4][4], alr[4][4];
    {
        const uint32_t* aH0 = AsH + rb * SSTR + tig;
        const uint32_t* aH1 = AsH + (rb + 8) * SSTR + tig;
        const uint32_t* aL0 = AsL + rb * SSTR + tig;
        const uint32_t* aL1 = AsL + (rb + 8) * SSTR + tig;
#pragma unroll
        for (int ks = 0; ks < 4; ks++) {
            const int kb = 8 * ks;
            ahr[ks][0] = aH0[kb];     ahr[ks][1] = aH1[kb];
            ahr[ks][2] = aH0[kb + 4]; ahr[ks][3] = aH1[kb + 4];
            alr[ks][0] = aL0[kb];     alr[ks][1] = aL1[kb];
            alr[ks][2] = aL0[kb + 4]; alr[ks][3] = aL1[kb + 4];
        }
    }

    // ---- store B0 -> buf1, stage B1
    *(uint4*)(buf1 + bn * SSTR + bkw)              = h0;
    *(uint4*)(buf1 + bn * SSTR + bkw + 4)          = h1;
    *(uint4*)(buf1 + 64 * SSTR + bn * SSTR + bkw)     = l0;
    *(uint4*)(buf1 + 64 * SSTR + bn * SSTR + bkw + 4) = l1;
    {
        const uint4* ph = (const uint4*)(g_WbH + 64 * KW) + tid * 2;
        const uint4* pl = (const uint4*)(g_WbL + 64 * KW) + tid * 2;
        h0 = ph[0]; h1 = ph[1]; l0 = pl[0]; l1 = pl[1];
    }
    __syncthreads();   // buf1 visible; all threads done hoisting from buf0

#pragma unroll 1
    for (int i = 0; i < 10; i++) {
        const int c0 = i * 64;
        uint32_t* cur  = (i & 1) ? buf0 : buf1;      // chunk i lives in buf[(i+1)&1]
        uint32_t* curH = cur;
        uint32_t* curL = cur + 64 * SSTR;

        float d[4][4];
#pragma unroll
        for (int j = 0; j < 4; j++)
#pragma unroll
            for (int q = 0; q < 4; q++) d[j][q] = 0.f;

#pragma unroll
        for (int ks = 0; ks < 4; ks++) {
            const int kb = 8 * ks;
#pragma unroll
            for (int j = 0; j < 4; j++) {
                const uint32_t* bh = curH + (wcol + 8 * j + gid) * SSTR + tig;
                const uint32_t* bl = curL + (wcol + 8 * j + gid) * SSTR + tig;
                uint32_t bhf[2], blf[2];
                bhf[0] = bh[kb]; bhf[1] = bh[kb + 4];
                blf[0] = bl[kb]; blf[1] = bl[kb + 4];
                mma_bf16(d[j], ahr[ks], bhf);
                mma_bf16(d[j], alr[ks], bhf);
                mma_bf16(d[j], ahr[ks], blf);
            }
        }

        // ---- store staged B(i+1) into the other buffer; stage B(i+2)
        if (i + 1 < 10) {
            uint32_t* nb = (i & 1) ? buf1 : buf0;
            *(uint4*)(nb + bn * SSTR + bkw)              = h0;
            *(uint4*)(nb + bn * SSTR + bkw + 4)          = h1;
            *(uint4*)(nb + 64 * SSTR + bn * SSTR + bkw)     = l0;
            *(uint4*)(nb + 64 * SSTR + bn * SSTR + bkw + 4) = l1;
            if (i + 2 < 10) {
                const uint4* ph = (const uint4*)(g_WbH + (i + 2) * 64 * KW) + tid * 2;
                const uint4* pl = (const uint4*)(g_WbL + (i + 2) * 64 * KW) + tid * 2;
                h0 = ph[0]; h1 = ph[1]; l0 = pl[0]; l1 = pl[1];
            }
        }

        // ---- epilogue for this chunk: route to g_z / out / g_P
        const int cb = tig * 2;
#pragma unroll
        for (int j = 0; j < 4; j++) {
            int gc = c0 + wcol + 8 * j + cb;
            if (gc >= TOTC) continue;
#pragma unroll
            for (int half = 0; half < 2; half++) {
                int node = r0 + 8 * half;
                if (node >= N_NODES) continue;
                float x = d[j][2 * half], y = d[j][2 * half + 1];
                if (gc < 64) {
                    *(float2*)(g_z + node * F + gc) = make_float2(x, y);
                } else if (gc < 384) {
                    *(float2*)(out + node * OUTC + (gc - 64)) = make_float2(x, y);
                } else {
#pragma unroll
                    for (int t = 0; t < 2; t++) {
                        int ix = gc - 384 + t;
                        int part = (ix >= 100) ? 8 : 0;
                        int pix  = (ix >= 100) ? ix - 100 : ix;
                        int rr = pix / 5, hh = pix % 5;
                        g_P[node * PSTRIDE + rr * 16 + part + hh] = t ? y : x;
                    }
                }
            }
        }
        __syncthreads();   // single per-chunk sync
    }
}

// ---------------------------------------------------------------------------
// gather v2: lane-distributed index prefetch (shfl) + direct red.v2 flushes.
// ---------------------------------------------------------------------------
__global__ void __launch_bounds__(256) gather_kernel(float* __restrict__ out)
{
    const int w = threadIdx.x >> 5, lane = threadIdx.x & 31;
    const int gw = blockIdx.x * 8 + w;
    const int e0 = gw * CHUNK;
    if (e0 >= N_EDGES) return;

    const unsigned pk_all = g_srcrt[e0 + lane];
    const int      dd_all = g_dstS [e0 + lane];

    float acc[10];
#pragma unroll
    for (int q = 0; q < 10; q++) acc[q] = 0.f;

    unsigned pk = __shfl_sync(0xffffffffu, pk_all, 0);
    int d_n = __shfl_sync(0xffffffffu, dd_all, 0);
    int s0 = pk & 0xFFFFu, rr0 = pk >> 16;
    float2 zs_n = *(const float2*)(g_z + s0 * F + 2 * lane);
    const float* pp = g_P + s0 * PSTRIDE + rr0 * 16;
    const float* qq = g_P + d_n * PSTRIDE + rr0 * 16 + 8;
    float4 ps4_n = *(const float4*)pp;  float ps1_n = pp[4];
    float4 pd4_n = *(const float4*)qq;  float pd1_n = qq[4];
    int d_cur = d_n;

#pragma unroll 4
    for (int i = 0; i < CHUNK; i++) {
        const int    d_c  = d_n;
        const float2 zs   = zs_n;
        const float4 ps4  = ps4_n, pd4 = pd4_n;
        const float  ps1  = ps1_n, pd1 = pd1_n;

        if (i + 1 < CHUNK) {
            unsigned pk2 = __shfl_sync(0xffffffffu, pk_all, i + 1);
            d_n = __shfl_sync(0xffffffffu, dd_all, i + 1);
            int s2 = pk2 & 0xFFFFu, r2 = pk2 >> 16;
            zs_n = *(const float2*)(g_z + s2 * F + 2 * lane);
            const float* p2 = g_P + s2 * PSTRIDE + r2 * 16;
            const float* p3 = g_P + d_n * PSTRIDE + r2 * 16 + 8;
            ps4_n = *(const float4*)p2;  ps1_n = p2[4];
            pd4_n = *(const float4*)p3;  pd1_n = p3[4];
        }

        if (d_c != d_cur) {   // warp-uniform: flush accumulator
            float* ob = out + (long)d_cur * OUTC + 2 * lane;
#pragma unroll
            for (int h = 0; h < NHEADS; h++)
                asm volatile("red.global.add.v2.f32 [%0], {%1, %2};"
                             :: "l"(ob + h * F), "f"(acc[2 * h]), "f"(acc[2 * h + 1])
                             : "memory");
#pragma unroll
            for (int q = 0; q < 10; q++) acc[q] = 0.f;
            d_cur = d_c;
        }

        float a0 = ps4.x + pd4.x;  a0 = a0 > 0.f ? a0 : 0.01f * a0;
        float a1 = ps4.y + pd4.y;  a1 = a1 > 0.f ? a1 : 0.01f * a1;
        float a2 = ps4.z + pd4.z;  a2 = a2 > 0.f ? a2 : 0.01f * a2;
        float a3 = ps4.w + pd4.w;  a3 = a3 > 0.f ? a3 : 0.01f * a3;
        float a4 = ps1   + pd1;    a4 = a4 > 0.f ? a4 : 0.01f * a4;
        acc[0] += a0 * zs.x;  acc[1] += a0 * zs.y;
        acc[2] += a1 * zs.x;  acc[3] += a1 * zs.y;
        acc[4] += a2 * zs.x;  acc[5] += a2 * zs.y;
        acc[6] += a3 * zs.x;  acc[7] += a3 * zs.y;
        acc[8] += a4 * zs.x;  acc[9] += a4 * zs.y;
    }

    float* ob = out + (long)d_cur * OUTC + 2 * lane;
#pragma unroll
    for (int h = 0; h < NHEADS; h++)
        asm volatile("red.global.add.v2.f32 [%0], {%1, %2};"
                     :: "l"(ob + h * F), "f"(acc[2 * h]), "f"(acc[2 * h + 1])
                     : "memory");
}

// ---------------------------------------------------------------------------
extern "C" void kernel_launch(void* const* d_in, const int* in_sizes, int n_in,
                              void* d_out, int out_size)
{
    const float* feat      = (const float*)d_in[0];
    const int*   src       = (const int*)  d_in[1];
    const int*   dst       = (const int*)  d_in[2];
    const int*   etype     = (const int*)  d_in[3];
    const float* fc_w      = (const float*)d_in[4];
    const float* self_fc_w = (const float*)d_in[5];
    const float* aw        = (const float*)d_in[6];
    const float* w_comp    = (const float*)d_in[7];
    float* out = (float*)d_out;

    const int NB = (N_NODES + 1023) / 1024;   // 25

    static cudaStream_t s_side = nullptr;
    static cudaEvent_t  ev_fork = nullptr, ev_sort = nullptr;
    if (s_side == nullptr) {
        cudaStreamCreateWithFlags(&s_side, cudaStreamNonBlocking);
        cudaEventCreateWithFlags(&ev_fork, cudaEventDisableTiming);
        cudaEventCreateWithFlags(&ev_sort, cudaEventDisableTiming);
        cudaFuncSetAttribute(proj_mma_kernel,
                             cudaFuncAttributeMaxDynamicSharedMemorySize, PROJ_SMEM);
    }

    // ---- fork: sort chain on side stream (independent of weights/proj)
    cudaEventRecord(ev_fork, 0);
    cudaStreamWaitEvent(s_side, ev_fork, 0);
    hist_kernel<<<(N_EDGES + 255) / 256, 256, 0, s_side>>>(dst);
    scan1_kernel<<<NB, 1024, 0, s_side>>>();
    scan3_kernel<<<NB, 1024, 0, s_side>>>();
    scatter_kernel<<<(N_EDGES + 255) / 256, 256, 0, s_side>>>(dst, src, etype);
    cudaEventRecord(ev_sort, s_side);

    // ---- main stream: weights -> projection GEMM
    split_w_kernel<<<(WCOLS * KW + 255) / 256, 256>>>(fc_w, self_fc_w);
    attn_comp_kernel<<<NRELS, 320>>>(aw, w_comp, fc_w);
    proj_mma_kernel<<<(N_NODES + 63) / 64, 256, PROJ_SMEM>>>(feat, out);

    // ---- join, then gather
    cudaStreamWaitEvent(0, ev_sort, 0);
    gather_kernel<<<(N_EDGES / CHUNK + 7) / 8, 256>>>(out);
}